// round 2
// baseline (speedup 1.0000x reference)
#include <cuda_runtime.h>
#include <cstdint>

#define Bz   128
#define Nn   196
#define DIMc 384
#define Kk   16
#define Hh   6
#define HD   64
#define DR   96
#define TM   14   // m-tile width; 14*14 == 196 exactly

// Scratch (device globals — allocation-free)
__device__ __align__(16) float g_wbt[(size_t)Nn * Nn * Kk];      // [n][m][k]
__device__ __align__(16) float g_mix[(size_t)Bz * Nn * Hh * Kk]; // [b][n][h][k]

typedef unsigned long long ull;

__device__ __forceinline__ ull fma2(ull a, ull b, ull c) {
    ull d;
    asm("fma.rn.f32x2 %0, %1, %2, %3;" : "=l"(d) : "l"(a), "l"(b), "l"(c));
    return d;
}
__device__ __forceinline__ ull pack2(float lo, float hi) {
    ull d;
    asm("mov.b64 %0, {%1, %2};" : "=l"(d) : "r"(__float_as_uint(lo)), "r"(__float_as_uint(hi)));
    return d;
}
__device__ __forceinline__ float2 unpack2(ull v) {
    unsigned lo, hi;
    asm("mov.b64 {%0, %1}, %2;" : "=r"(lo), "=r"(hi) : "l"(v));
    return make_float2(__uint_as_float(lo), __uint_as_float(hi));
}

// ---------------------------------------------------------------------------
// Kernel 1: weight_bank [k][n][m] -> g_wbt [n][m][k]  (k contiguous)
// ---------------------------------------------------------------------------
extern "C" __global__ void transpose_wb_kernel(const float* __restrict__ wb) {
    int t = blockIdx.x * 256 + threadIdx.x;
    if (t >= Nn * Nn) return;
    int n = t / Nn, m = t % Nn;
    float v[Kk];
#pragma unroll
    for (int k = 0; k < Kk; ++k)
        v[k] = wb[((size_t)k * Nn + n) * Nn + m];   // coalesced over m
    float4* dst = (float4*)&g_wbt[(size_t)t * Kk];
    dst[0] = make_float4(v[0],  v[1],  v[2],  v[3]);
    dst[1] = make_float4(v[4],  v[5],  v[6],  v[7]);
    dst[2] = make_float4(v[8],  v[9],  v[10], v[11]);
    dst[3] = make_float4(v[12], v[13], v[14], v[15]);
}

// ---------------------------------------------------------------------------
// Kernel 2: adapter.  64 rows/block, 192 threads (12 colgroups x 16 rowgroups)
// hid = gelu(x@W1+b1); mix = hid@W2+b2; softmax over k; -> g_mix[b][n][h][k]
// smem: Ws 9216 floats (W1 tile / W2 / Ms), Xs 96*68 floats (X tile / Hs)
// ---------------------------------------------------------------------------
#define AD_SMEM_FLOATS (9216 + 96*68)

extern "C" __global__ void __launch_bounds__(192)
adapter_kernel(const float* __restrict__ x,
               const float* __restrict__ W1, const float* __restrict__ b1,
               const float* __restrict__ W2, const float* __restrict__ b2) {
    extern __shared__ float sm[];
    float* Ws = sm;            // 9216 floats (96x96)
    float* Xs = sm + 9216;     // 96 x 68 (padded), reused as Hs

    const int t   = threadIdx.x;
    const int tc  = t % 12;           // col group
    const int rg  = t / 12;           // row group
    const int j0  = tc * 8;
    const int r0  = rg * 4;
    const int row0 = blockIdx.x * 64; // 392 blocks * 64 = 25088 rows

    ull acc[4][4];
#pragma unroll
    for (int r = 0; r < 4; ++r)
#pragma unroll
        for (int p = 0; p < 4; ++p) acc[r][p] = 0ull;

    // ---- phase 1: hid = x @ W1 over 4 i-tiles of 96 ----
    for (int it = 0; it < 4; ++it) {
        __syncthreads();
        for (int idx = t; idx < 9216; idx += 192)
            Ws[idx] = W1[(size_t)it * 96 * 96 + idx];          // contiguous rows
        for (int idx = t; idx < 6144; idx += 192) {
            int il = idx % 96, r = idx / 96;
            Xs[il * 68 + r] = x[(size_t)(row0 + r) * DIMc + it * 96 + il];
        }
        __syncthreads();
#pragma unroll 4
        for (int il = 0; il < 96; ++il) {
            const ulonglong2 wA = *(const ulonglong2*)&Ws[il * 96 + j0];
            const ulonglong2 wB = *(const ulonglong2*)&Ws[il * 96 + j0 + 4];
            const float4 xv = *(const float4*)&Xs[il * 68 + r0];
            ull xd0 = pack2(xv.x, xv.x), xd1 = pack2(xv.y, xv.y);
            ull xd2 = pack2(xv.z, xv.z), xd3 = pack2(xv.w, xv.w);
            acc[0][0] = fma2(wA.x, xd0, acc[0][0]);
            acc[0][1] = fma2(wA.y, xd0, acc[0][1]);
            acc[0][2] = fma2(wB.x, xd0, acc[0][2]);
            acc[0][3] = fma2(wB.y, xd0, acc[0][3]);
            acc[1][0] = fma2(wA.x, xd1, acc[1][0]);
            acc[1][1] = fma2(wA.y, xd1, acc[1][1]);
            acc[1][2] = fma2(wB.x, xd1, acc[1][2]);
            acc[1][3] = fma2(wB.y, xd1, acc[1][3]);
            acc[2][0] = fma2(wA.x, xd2, acc[2][0]);
            acc[2][1] = fma2(wA.y, xd2, acc[2][1]);
            acc[2][2] = fma2(wB.x, xd2, acc[2][2]);
            acc[2][3] = fma2(wB.y, xd2, acc[2][3]);
            acc[3][0] = fma2(wA.x, xd3, acc[3][0]);
            acc[3][1] = fma2(wA.y, xd3, acc[3][1]);
            acc[3][2] = fma2(wB.x, xd3, acc[3][2]);
            acc[3][3] = fma2(wB.y, xd3, acc[3][3]);
        }
    }
    __syncthreads();

    // ---- GELU(exact) + write Hs (transposed) ; load W2 into Ws ----
    for (int idx = t; idx < 9216; idx += 192) Ws[idx] = W2[idx];
    float* Hs = Xs;  // [i up to 96][68]
#pragma unroll
    for (int r = 0; r < 4; ++r)
#pragma unroll
        for (int p = 0; p < 4; ++p) {
            float2 v = unpack2(acc[r][p]);
            int j = j0 + 2 * p;
            float a0 = v.x + b1[j];
            float a1 = v.y + b1[j + 1];
            a0 = 0.5f * a0 * (1.0f + erff(a0 * 0.7071067811865476f));
            a1 = 0.5f * a1 * (1.0f + erff(a1 * 0.7071067811865476f));
            Hs[(size_t)j       * 68 + r0 + r] = a0;
            Hs[(size_t)(j + 1) * 68 + r0 + r] = a1;
        }
    __syncthreads();

    // ---- phase 2: mix = hid @ W2 ----
    ull acc2[4][4];
#pragma unroll
    for (int r = 0; r < 4; ++r)
#pragma unroll
        for (int p = 0; p < 4; ++p) acc2[r][p] = 0ull;
#pragma unroll 4
    for (int i = 0; i < 96; ++i) {
        const ulonglong2 wA = *(const ulonglong2*)&Ws[i * 96 + j0];
        const ulonglong2 wB = *(const ulonglong2*)&Ws[i * 96 + j0 + 4];
        const float4 hv = *(const float4*)&Hs[i * 68 + r0];
        ull xd0 = pack2(hv.x, hv.x), xd1 = pack2(hv.y, hv.y);
        ull xd2 = pack2(hv.z, hv.z), xd3 = pack2(hv.w, hv.w);
        acc2[0][0] = fma2(wA.x, xd0, acc2[0][0]);
        acc2[0][1] = fma2(wA.y, xd0, acc2[0][1]);
        acc2[0][2] = fma2(wB.x, xd0, acc2[0][2]);
        acc2[0][3] = fma2(wB.y, xd0, acc2[0][3]);
        acc2[1][0] = fma2(wA.x, xd1, acc2[1][0]);
        acc2[1][1] = fma2(wA.y, xd1, acc2[1][1]);
        acc2[1][2] = fma2(wB.x, xd1, acc2[1][2]);
        acc2[1][3] = fma2(wB.y, xd1, acc2[1][3]);
        acc2[2][0] = fma2(wA.x, xd2, acc2[2][0]);
        acc2[2][1] = fma2(wA.y, xd2, acc2[2][1]);
        acc2[2][2] = fma2(wB.x, xd2, acc2[2][2]);
        acc2[2][3] = fma2(wB.y, xd2, acc2[2][3]);
        acc2[3][0] = fma2(wA.x, xd3, acc2[3][0]);
        acc2[3][1] = fma2(wA.y, xd3, acc2[3][1]);
        acc2[3][2] = fma2(wB.x, xd3, acc2[3][2]);
        acc2[3][3] = fma2(wB.y, xd3, acc2[3][3]);
    }
    __syncthreads();   // done reading Ws(W2)

    // ---- + b2, stage to Ms, softmax over k ----
    float* Ms = Ws;  // 64*96 floats
#pragma unroll
    for (int r = 0; r < 4; ++r)
#pragma unroll
        for (int p = 0; p < 4; ++p) {
            float2 v = unpack2(acc2[r][p]);
            int j = j0 + 2 * p;
            Ms[(r0 + r) * 96 + j]     = v.x + b2[j];
            Ms[(r0 + r) * 96 + j + 1] = v.y + b2[j + 1];
        }
    __syncthreads();

    for (int g = t; g < 384; g += 192) {
        int r = g / 6, h = g % 6;
        float vals[Kk];
        float vmax = -1e30f;
#pragma unroll
        for (int k = 0; k < Kk; ++k) {
            vals[k] = Ms[r * 96 + k * Hh + h];
            vmax = fmaxf(vmax, vals[k]);
        }
        float s = 0.f;
#pragma unroll
        for (int k = 0; k < Kk; ++k) { vals[k] = __expf(vals[k] - vmax); s += vals[k]; }
        float inv = 1.0f / s;
        size_t base = ((size_t)(row0 + r) * Hh + h) * Kk;
#pragma unroll
        for (int k = 0; k < Kk; ++k) g_mix[base + k] = vals[k] * inv;
    }
}

// ---------------------------------------------------------------------------
// Kernel 3: fused mixer.  Block = (m-tile of 14, batch b), 384 threads.
//   phase 1: w_s[n][h][m] = sum_k mix[b,n,h,k] * wbt[n,mg,k]
//   phase 2: out[b,mg,h,c] = sum_n w_s[n][h][m] * x[b,n,h,c]
// smem: mix_s 18816 floats + w_s 18816 floats = 150528 B
// ---------------------------------------------------------------------------
#define MX_SMEM_FLOATS (18816 + 18816)

extern "C" __global__ void __launch_bounds__(384, 1)
mixer_kernel(const float* __restrict__ x, float* __restrict__ out) {
    extern __shared__ float sm[];
    float* mix_s = sm;            // [n][h][k]   (copy of g_mix[b])
    float* w_s   = sm + 18816;    // [n][h][16]  (m padded 14->16)

    const int t  = threadIdx.x;
    const int b  = blockIdx.y;
    const int mt = blockIdx.x;    // 0..13

    // stage mix[b] into smem
    {
        const float4* src = (const float4*)&g_mix[(size_t)b * Nn * 96];
        float4* dst = (float4*)mix_s;
        for (int idx = t; idx < 4704; idx += 384) dst[idx] = src[idx];
    }
    __syncthreads();

    // phase 1: per (n, m) compute 6 dot16s
    for (int p = t; p < Nn * TM; p += 384) {
        int n = p / TM, ml = p % TM;
        int mg = mt * TM + ml;
        const float4* wv = (const float4*)&g_wbt[((size_t)n * Nn + mg) * Kk];
        float4 w0 = wv[0], w1 = wv[1], w2 = wv[2], w3 = wv[3];
#pragma unroll
        for (int h = 0; h < Hh; ++h) {
            const float4* mx = (const float4*)&mix_s[n * 96 + h * Kk];
            float4 m0 = mx[0], m1 = mx[1], m2 = mx[2], m3 = mx[3];
            float s = w0.x * m0.x;
            s = fmaf(w0.y, m0.y, s); s = fmaf(w0.z, m0.z, s); s = fmaf(w0.w, m0.w, s);
            s = fmaf(w1.x, m1.x, s); s = fmaf(w1.y, m1.y, s); s = fmaf(w1.z, m1.z, s); s = fmaf(w1.w, m1.w, s);
            s = fmaf(w2.x, m2.x, s); s = fmaf(w2.y, m2.y, s); s = fmaf(w2.z, m2.z, s); s = fmaf(w2.w, m2.w, s);
            s = fmaf(w3.x, m3.x, s); s = fmaf(w3.y, m3.y, s); s = fmaf(w3.z, m3.z, s); s = fmaf(w3.w, m3.w, s);
            w_s[(n * Hh + h) * 16 + ml] = s;
        }
    }
    __syncthreads();

    // phase 2: stream x, accumulate 14 m's per thread as 7 f32x2 pairs
    const int h = t >> 6;   // channel = t = h*64 + c
    ull acc[7];
#pragma unroll
    for (int q = 0; q < 7; ++q) acc[q] = 0ull;

    const float* xb = x + (size_t)b * Nn * DIMc + t;
#pragma unroll 2
    for (int n = 0; n < Nn; ++n) {
        float xv = xb[(size_t)n * DIMc];
        ull xx = pack2(xv, xv);
        const float* wr = &w_s[(n * Hh + h) * 16];
        ulonglong2 wA = *(const ulonglong2*)&wr[0];
        ulonglong2 wB = *(const ulonglong2*)&wr[4];
        ulonglong2 wC = *(const ulonglong2*)&wr[8];
        ull        wD = *(const ull*)&wr[12];
        acc[0] = fma2(wA.x, xx, acc[0]);
        acc[1] = fma2(wA.y, xx, acc[1]);
        acc[2] = fma2(wB.x, xx, acc[2]);
        acc[3] = fma2(wB.y, xx, acc[3]);
        acc[4] = fma2(wC.x, xx, acc[4]);
        acc[5] = fma2(wC.y, xx, acc[5]);
        acc[6] = fma2(wD,   xx, acc[6]);
    }

    float* ob = out + ((size_t)b * Nn + mt * TM) * DIMc + t;
#pragma unroll
    for (int q = 0; q < 7; ++q) {
        float2 v = unpack2(acc[q]);
        ob[(size_t)(2 * q)     * DIMc] = v.x;
        ob[(size_t)(2 * q + 1) * DIMc] = v.y;
    }
}

// ---------------------------------------------------------------------------
extern "C" void kernel_launch(void* const* d_in, const int* in_sizes, int n_in,
                              void* d_out, int out_size) {
    const float* x  = (const float*)d_in[0];
    const float* W1 = (const float*)d_in[1];
    const float* b1 = (const float*)d_in[2];
    const float* W2 = (const float*)d_in[3];
    const float* b2 = (const float*)d_in[4];
    const float* wb = (const float*)d_in[5];
    float* out = (float*)d_out;

    cudaFuncSetAttribute((const void*)adapter_kernel,
                         cudaFuncAttributeMaxDynamicSharedMemorySize,
                         AD_SMEM_FLOATS * 4);
    cudaFuncSetAttribute((const void*)mixer_kernel,
                         cudaFuncAttributeMaxDynamicSharedMemorySize,
                         MX_SMEM_FLOATS * 4);

    transpose_wb_kernel<<<(Nn * Nn + 255) / 256, 256>>>(wb);
    adapter_kernel<<<392, 192, AD_SMEM_FLOATS * 4>>>(x, W1, b1, W2, b2);
    mixer_kernel<<<dim3(TM, Bz), 384, MX_SMEM_FLOATS * 4>>>(x, out);
}

// round 3
// speedup vs baseline: 1.5332x; 1.5332x over previous
#include <cuda_runtime.h>
#include <cstdint>

#define Bz   128
#define Nn   196
#define DIMc 384
#define Kk   16
#define Hh   6
#define HD   64
#define DR   96
#define TM   14   // m-tile width; 14*14 == 196
#define CH   28   // n-chunk in mixer; 7*28 == 196
#define NCH  7

// Scratch (device globals — allocation-free)
__device__ __align__(16) float g_wbt[(size_t)Nn * Nn * Kk];      // [n][m][k]
__device__ __align__(16) float g_mix[(size_t)Bz * Nn * Hh * Kk]; // [b][n][h][k]

typedef unsigned long long ull;

__device__ __forceinline__ ull fma2(ull a, ull b, ull c) {
    ull d;
    asm("fma.rn.f32x2 %0, %1, %2, %3;" : "=l"(d) : "l"(a), "l"(b), "l"(c));
    return d;
}
__device__ __forceinline__ ull pack2(float lo, float hi) {
    ull d;
    asm("mov.b64 %0, {%1, %2};" : "=l"(d) : "r"(__float_as_uint(lo)), "r"(__float_as_uint(hi)));
    return d;
}
__device__ __forceinline__ float2 unpack2(ull v) {
    unsigned lo, hi;
    asm("mov.b64 {%0, %1}, %2;" : "=r"(lo), "=r"(hi) : "l"(v));
    return make_float2(__uint_as_float(lo), __uint_as_float(hi));
}

// ---------------------------------------------------------------------------
// Kernel 1: weight_bank [k][n][m] -> g_wbt [n][m][k]  (k contiguous)
// ---------------------------------------------------------------------------
extern "C" __global__ void transpose_wb_kernel(const float* __restrict__ wb) {
    int t = blockIdx.x * 256 + threadIdx.x;
    if (t >= Nn * Nn) return;
    int n = t / Nn, m = t % Nn;
    float v[Kk];
#pragma unroll
    for (int k = 0; k < Kk; ++k)
        v[k] = wb[((size_t)k * Nn + n) * Nn + m];   // coalesced over m
    float4* dst = (float4*)&g_wbt[(size_t)t * Kk];
    dst[0] = make_float4(v[0],  v[1],  v[2],  v[3]);
    dst[1] = make_float4(v[4],  v[5],  v[6],  v[7]);
    dst[2] = make_float4(v[8],  v[9],  v[10], v[11]);
    dst[3] = make_float4(v[12], v[13], v[14], v[15]);
}

// ---------------------------------------------------------------------------
// Kernel 2: adapter.  64 rows/block, 192 threads (12 colgroups x 16 rowgroups)
// hid = gelu(x@W1+b1); mix = hid@W2+b2; softmax over k; -> g_mix[b][n][h][k]
// ---------------------------------------------------------------------------
#define AD_SMEM_FLOATS (9216 + 96*68)

extern "C" __global__ void __launch_bounds__(192)
adapter_kernel(const float* __restrict__ x,
               const float* __restrict__ W1, const float* __restrict__ b1,
               const float* __restrict__ W2, const float* __restrict__ b2) {
    extern __shared__ float sm[];
    float* Ws = sm;            // 9216 floats (96x96)
    float* Xs = sm + 9216;     // 96 x 68 (padded), reused as Hs

    const int t   = threadIdx.x;
    const int tc  = t % 12;           // col group
    const int rg  = t / 12;           // row group
    const int j0  = tc * 8;
    const int r0  = rg * 4;
    const int row0 = blockIdx.x * 64; // 392 blocks * 64 = 25088 rows

    ull acc[4][4];
#pragma unroll
    for (int r = 0; r < 4; ++r)
#pragma unroll
        for (int p = 0; p < 4; ++p) acc[r][p] = 0ull;

    // ---- phase 1: hid = x @ W1 over 4 i-tiles of 96 ----
    for (int it = 0; it < 4; ++it) {
        __syncthreads();
        for (int idx = t; idx < 9216; idx += 192)
            Ws[idx] = W1[(size_t)it * 96 * 96 + idx];
        for (int idx = t; idx < 6144; idx += 192) {
            int il = idx % 96, r = idx / 96;
            Xs[il * 68 + r] = x[(size_t)(row0 + r) * DIMc + it * 96 + il];
        }
        __syncthreads();
#pragma unroll 4
        for (int il = 0; il < 96; ++il) {
            const ulonglong2 wA = *(const ulonglong2*)&Ws[il * 96 + j0];
            const ulonglong2 wB = *(const ulonglong2*)&Ws[il * 96 + j0 + 4];
            const float4 xv = *(const float4*)&Xs[il * 68 + r0];
            ull xd0 = pack2(xv.x, xv.x), xd1 = pack2(xv.y, xv.y);
            ull xd2 = pack2(xv.z, xv.z), xd3 = pack2(xv.w, xv.w);
            acc[0][0] = fma2(wA.x, xd0, acc[0][0]);
            acc[0][1] = fma2(wA.y, xd0, acc[0][1]);
            acc[0][2] = fma2(wB.x, xd0, acc[0][2]);
            acc[0][3] = fma2(wB.y, xd0, acc[0][3]);
            acc[1][0] = fma2(wA.x, xd1, acc[1][0]);
            acc[1][1] = fma2(wA.y, xd1, acc[1][1]);
            acc[1][2] = fma2(wB.x, xd1, acc[1][2]);
            acc[1][3] = fma2(wB.y, xd1, acc[1][3]);
            acc[2][0] = fma2(wA.x, xd2, acc[2][0]);
            acc[2][1] = fma2(wA.y, xd2, acc[2][1]);
            acc[2][2] = fma2(wB.x, xd2, acc[2][2]);
            acc[2][3] = fma2(wB.y, xd2, acc[2][3]);
            acc[3][0] = fma2(wA.x, xd3, acc[3][0]);
            acc[3][1] = fma2(wA.y, xd3, acc[3][1]);
            acc[3][2] = fma2(wB.x, xd3, acc[3][2]);
            acc[3][3] = fma2(wB.y, xd3, acc[3][3]);
        }
    }
    __syncthreads();

    // ---- GELU(exact) + write Hs (transposed) ; load W2 into Ws ----
    for (int idx = t; idx < 9216; idx += 192) Ws[idx] = W2[idx];
    float* Hs = Xs;
#pragma unroll
    for (int r = 0; r < 4; ++r)
#pragma unroll
        for (int p = 0; p < 4; ++p) {
            float2 v = unpack2(acc[r][p]);
            int j = j0 + 2 * p;
            float a0 = v.x + b1[j];
            float a1 = v.y + b1[j + 1];
            a0 = 0.5f * a0 * (1.0f + erff(a0 * 0.7071067811865476f));
            a1 = 0.5f * a1 * (1.0f + erff(a1 * 0.7071067811865476f));
            Hs[(size_t)j       * 68 + r0 + r] = a0;
            Hs[(size_t)(j + 1) * 68 + r0 + r] = a1;
        }
    __syncthreads();

    // ---- phase 2: mix = hid @ W2 ----
    ull acc2[4][4];
#pragma unroll
    for (int r = 0; r < 4; ++r)
#pragma unroll
        for (int p = 0; p < 4; ++p) acc2[r][p] = 0ull;
#pragma unroll 4
    for (int i = 0; i < 96; ++i) {
        const ulonglong2 wA = *(const ulonglong2*)&Ws[i * 96 + j0];
        const ulonglong2 wB = *(const ulonglong2*)&Ws[i * 96 + j0 + 4];
        const float4 hv = *(const float4*)&Hs[i * 68 + r0];
        ull xd0 = pack2(hv.x, hv.x), xd1 = pack2(hv.y, hv.y);
        ull xd2 = pack2(hv.z, hv.z), xd3 = pack2(hv.w, hv.w);
        acc2[0][0] = fma2(wA.x, xd0, acc2[0][0]);
        acc2[0][1] = fma2(wA.y, xd0, acc2[0][1]);
        acc2[0][2] = fma2(wB.x, xd0, acc2[0][2]);
        acc2[0][3] = fma2(wB.y, xd0, acc2[0][3]);
        acc2[1][0] = fma2(wA.x, xd1, acc2[1][0]);
        acc2[1][1] = fma2(wA.y, xd1, acc2[1][1]);
        acc2[1][2] = fma2(wB.x, xd1, acc2[1][2]);
        acc2[1][3] = fma2(wB.y, xd1, acc2[1][3]);
        acc2[2][0] = fma2(wA.x, xd2, acc2[2][0]);
        acc2[2][1] = fma2(wA.y, xd2, acc2[2][1]);
        acc2[2][2] = fma2(wB.x, xd2, acc2[2][2]);
        acc2[2][3] = fma2(wB.y, xd2, acc2[2][3]);
        acc2[3][0] = fma2(wA.x, xd3, acc2[3][0]);
        acc2[3][1] = fma2(wA.y, xd3, acc2[3][1]);
        acc2[3][2] = fma2(wB.x, xd3, acc2[3][2]);
        acc2[3][3] = fma2(wB.y, xd3, acc2[3][3]);
    }
    __syncthreads();

    // ---- + b2, stage to Ms, softmax over k ----
    float* Ms = Ws;
#pragma unroll
    for (int r = 0; r < 4; ++r)
#pragma unroll
        for (int p = 0; p < 4; ++p) {
            float2 v = unpack2(acc2[r][p]);
            int j = j0 + 2 * p;
            Ms[(r0 + r) * 96 + j]     = v.x + b2[j];
            Ms[(r0 + r) * 96 + j + 1] = v.y + b2[j + 1];
        }
    __syncthreads();

    for (int g = t; g < 384; g += 192) {
        int r = g / 6, h = g % 6;
        float vals[Kk];
        float vmax = -1e30f;
#pragma unroll
        for (int k = 0; k < Kk; ++k) {
            vals[k] = Ms[r * 96 + k * Hh + h];
            vmax = fmaxf(vmax, vals[k]);
        }
        float s = 0.f;
#pragma unroll
        for (int k = 0; k < Kk; ++k) { vals[k] = __expf(vals[k] - vmax); s += vals[k]; }
        float inv = 1.0f / s;
        size_t base = ((size_t)(row0 + r) * Hh + h) * Kk;
#pragma unroll
        for (int k = 0; k < Kk; ++k) g_mix[base + k] = vals[k] * inv;
    }
}

// ---------------------------------------------------------------------------
// Kernel 3: fused mixer v2 — n chunked by 28, all phase-2 operands in smem.
// Block = (m-tile mt of 14, batch b), 384 threads, 2 CTAs/SM.
// per chunk c (n0 = 28c):
//   stage xs[28][384]           (coalesced float4 from x[b])
//   stage wb_s[28][14][16]      (from g_wbt, k-contiguous)
//   phase1: ws[nl][h][16(m pad)] = sum_k mix[b,n,h,k] * wb_s[nl][ml][k]
//   phase2: acc[7 f32x2 pairs over 14 m] += ws row * xs[nl][t]
// smem = 10752 + 6272 + 2688 floats = 78848 B
// ---------------------------------------------------------------------------
#define MX_XS   10752
#define MX_WB   6272
#define MX_WS   2688
#define MX_SMEM_FLOATS (MX_XS + MX_WB + MX_WS)

extern "C" __global__ void __launch_bounds__(384, 2)
mixer_kernel(const float* __restrict__ x, float* __restrict__ out) {
    extern __shared__ float sm[];
    float* xs   = sm;                  // [nl][384]
    float* wb_s = sm + MX_XS;          // [nl][ml][16]
    float* ws   = sm + MX_XS + MX_WB;  // [nl][h][16]

    const int t  = threadIdx.x;
    const int b  = blockIdx.y;
    const int mt = blockIdx.x;    // 0..13
    const int h  = t >> 6;

    ull acc[7];
#pragma unroll
    for (int q = 0; q < 7; ++q) acc[q] = 0ull;

    for (int c = 0; c < NCH; ++c) {
        const int n0 = c * CH;
        __syncthreads();
        // stage x chunk: 28*384 floats = 2688 float4, 7 per thread
        {
            const float4* src = (const float4*)(x + ((size_t)b * Nn + n0) * DIMc);
            float4* dst = (float4*)xs;
#pragma unroll
            for (int i = 0; i < 7; ++i) dst[t + i * 384] = src[t + i * 384];
        }
        // stage wbt chunk: 28*14*16 floats = 1568 float4
        {
            const float4* src = (const float4*)g_wbt;
            float4* dst = (float4*)wb_s;
            for (int idx = t; idx < 1568; idx += 384) {
                int pos = idx >> 2, q = idx & 3;
                int nl = pos / TM, ml = pos - nl * TM;
                dst[idx] = src[(((n0 + nl) * Nn + mt * TM + ml) << 2) + q];
            }
        }
        __syncthreads();
        // phase 1: 336 active threads; each handles (nl, hh) for 7 m's
        if (t < 336) {
            int nl = t / 12, sub = t - nl * 12;
            int hh = sub >> 1, m0 = (sub & 1) * 7;
            const float4* mx = (const float4*)&g_mix[(((size_t)b * Nn + n0 + nl) * Hh + hh) * Kk];
            float4 a0 = mx[0], a1 = mx[1], a2 = mx[2], a3 = mx[3];
#pragma unroll
            for (int ml = m0; ml < m0 + 7; ++ml) {
                const float4* wv = (const float4*)&wb_s[(nl * TM + ml) * Kk];
                float4 w0 = wv[0], w1 = wv[1], w2 = wv[2], w3 = wv[3];
                float s = w0.x * a0.x;
                s = fmaf(w0.y, a0.y, s); s = fmaf(w0.z, a0.z, s); s = fmaf(w0.w, a0.w, s);
                s = fmaf(w1.x, a1.x, s); s = fmaf(w1.y, a1.y, s); s = fmaf(w1.z, a1.z, s); s = fmaf(w1.w, a1.w, s);
                s = fmaf(w2.x, a2.x, s); s = fmaf(w2.y, a2.y, s); s = fmaf(w2.z, a2.z, s); s = fmaf(w2.w, a2.w, s);
                s = fmaf(w3.x, a3.x, s); s = fmaf(w3.y, a3.y, s); s = fmaf(w3.z, a3.z, s); s = fmaf(w3.w, a3.w, s);
                ws[(nl * Hh + hh) * 16 + ml] = s;
            }
        }
        __syncthreads();
        // phase 2: all operands in smem
#pragma unroll 4
        for (int nl = 0; nl < CH; ++nl) {
            float xv = xs[nl * 384 + t];
            ull xx = pack2(xv, xv);
            const float* wr = &ws[(nl * Hh + h) * 16];
            ulonglong2 wA = *(const ulonglong2*)&wr[0];
            ulonglong2 wB = *(const ulonglong2*)&wr[4];
            ulonglong2 wC = *(const ulonglong2*)&wr[8];
            ull        wD = *(const ull*)&wr[12];
            acc[0] = fma2(wA.x, xx, acc[0]);
            acc[1] = fma2(wA.y, xx, acc[1]);
            acc[2] = fma2(wB.x, xx, acc[2]);
            acc[3] = fma2(wB.y, xx, acc[3]);
            acc[4] = fma2(wC.x, xx, acc[4]);
            acc[5] = fma2(wC.y, xx, acc[5]);
            acc[6] = fma2(wD,   xx, acc[6]);
        }
    }

    float* ob = out + ((size_t)b * Nn + mt * TM) * DIMc + t;
#pragma unroll
    for (int q = 0; q < 7; ++q) {
        float2 v = unpack2(acc[q]);
        ob[(size_t)(2 * q)     * DIMc] = v.x;
        ob[(size_t)(2 * q + 1) * DIMc] = v.y;
    }
}

// ---------------------------------------------------------------------------
extern "C" void kernel_launch(void* const* d_in, const int* in_sizes, int n_in,
                              void* d_out, int out_size) {
    const float* x  = (const float*)d_in[0];
    const float* W1 = (const float*)d_in[1];
    const float* b1 = (const float*)d_in[2];
    const float* W2 = (const float*)d_in[3];
    const float* b2 = (const float*)d_in[4];
    const float* wb = (const float*)d_in[5];
    float* out = (float*)d_out;

    cudaFuncSetAttribute((const void*)adapter_kernel,
                         cudaFuncAttributeMaxDynamicSharedMemorySize,
                         AD_SMEM_FLOATS * 4);
    cudaFuncSetAttribute((const void*)mixer_kernel,
                         cudaFuncAttributeMaxDynamicSharedMemorySize,
                         MX_SMEM_FLOATS * 4);

    // Order: adapter, transpose, mixer — so ncu's skip-5 capture lands on the
    // mixer (launch index 5) while preserving dependencies (stream-ordered).
    adapter_kernel<<<392, 192, AD_SMEM_FLOATS * 4>>>(x, W1, b1, W2, b2);
    transpose_wb_kernel<<<(Nn * Nn + 255) / 256, 256>>>(wb);
    mixer_kernel<<<dim3(TM, Bz), 384, MX_SMEM_FLOATS * 4>>>(x, out);
}

// round 4
// speedup vs baseline: 1.5347x; 1.0010x over previous
#include <cuda_runtime.h>
#include <cstdint>

#define Bz   128
#define Nn   196
#define DIMc 384
#define Kk   16
#define Hh   6
#define HD   64
#define DR   96
#define TM   14   // m-tile width; 14*14 == 196
#define CH   28   // n-chunk in mixer; 7*28 == 196
#define NCH  7

// Scratch (device globals — allocation-free)
__device__ __align__(16) float g_wbt[(size_t)Nn * Nn * Kk];      // [n][m][k]
__device__ __align__(16) float g_mix[(size_t)Bz * Nn * Hh * Kk]; // [b][n][h][k]

typedef unsigned long long ull;

__device__ __forceinline__ ull fma2(ull a, ull b, ull c) {
    ull d;
    asm("fma.rn.f32x2 %0, %1, %2, %3;" : "=l"(d) : "l"(a), "l"(b), "l"(c));
    return d;
}
__device__ __forceinline__ ull pack2(float lo, float hi) {
    ull d;
    asm("mov.b64 %0, {%1, %2};" : "=l"(d) : "r"(__float_as_uint(lo)), "r"(__float_as_uint(hi)));
    return d;
}
__device__ __forceinline__ float2 unpack2(ull v) {
    unsigned lo, hi;
    asm("mov.b64 {%0, %1}, %2;" : "=r"(lo), "=r"(hi) : "l"(v));
    return make_float2(__uint_as_float(lo), __uint_as_float(hi));
}

// ---------------------------------------------------------------------------
// Kernel 1: weight_bank [k][n][m] -> g_wbt [n][m][k]  (k contiguous)
// ---------------------------------------------------------------------------
extern "C" __global__ void transpose_wb_kernel(const float* __restrict__ wb) {
    int t = blockIdx.x * 256 + threadIdx.x;
    if (t >= Nn * Nn) return;
    int n = t / Nn, m = t % Nn;
    float v[Kk];
#pragma unroll
    for (int k = 0; k < Kk; ++k)
        v[k] = wb[((size_t)k * Nn + n) * Nn + m];   // coalesced over m
    float4* dst = (float4*)&g_wbt[(size_t)t * Kk];
    dst[0] = make_float4(v[0],  v[1],  v[2],  v[3]);
    dst[1] = make_float4(v[4],  v[5],  v[6],  v[7]);
    dst[2] = make_float4(v[8],  v[9],  v[10], v[11]);
    dst[3] = make_float4(v[12], v[13], v[14], v[15]);
}

// ---------------------------------------------------------------------------
// Kernel 2: adapter.  64 rows/block, 192 threads (12 colgroups x 16 rowgroups)
// hid = gelu(x@W1+b1); mix = hid@W2+b2; softmax over k; -> g_mix[b][n][h][k]
// ---------------------------------------------------------------------------
#define AD_SMEM_FLOATS (9216 + 96*68)

extern "C" __global__ void __launch_bounds__(192)
adapter_kernel(const float* __restrict__ x,
               const float* __restrict__ W1, const float* __restrict__ b1,
               const float* __restrict__ W2, const float* __restrict__ b2) {
    extern __shared__ float sm[];
    float* Ws = sm;            // 9216 floats (96x96)
    float* Xs = sm + 9216;     // 96 x 68 (padded), reused as Hs

    const int t   = threadIdx.x;
    const int tc  = t % 12;           // col group
    const int rg  = t / 12;           // row group
    const int j0  = tc * 8;
    const int r0  = rg * 4;
    const int row0 = blockIdx.x * 64; // 392 blocks * 64 = 25088 rows

    ull acc[4][4];
#pragma unroll
    for (int r = 0; r < 4; ++r)
#pragma unroll
        for (int p = 0; p < 4; ++p) acc[r][p] = 0ull;

    // ---- phase 1: hid = x @ W1 over 4 i-tiles of 96 ----
    for (int it = 0; it < 4; ++it) {
        __syncthreads();
        for (int idx = t; idx < 9216; idx += 192)
            Ws[idx] = W1[(size_t)it * 96 * 96 + idx];
        for (int idx = t; idx < 6144; idx += 192) {
            int il = idx % 96, r = idx / 96;
            Xs[il * 68 + r] = x[(size_t)(row0 + r) * DIMc + it * 96 + il];
        }
        __syncthreads();
#pragma unroll 4
        for (int il = 0; il < 96; ++il) {
            const ulonglong2 wA = *(const ulonglong2*)&Ws[il * 96 + j0];
            const ulonglong2 wB = *(const ulonglong2*)&Ws[il * 96 + j0 + 4];
            const float4 xv = *(const float4*)&Xs[il * 68 + r0];
            ull xd0 = pack2(xv.x, xv.x), xd1 = pack2(xv.y, xv.y);
            ull xd2 = pack2(xv.z, xv.z), xd3 = pack2(xv.w, xv.w);
            acc[0][0] = fma2(wA.x, xd0, acc[0][0]);
            acc[0][1] = fma2(wA.y, xd0, acc[0][1]);
            acc[0][2] = fma2(wB.x, xd0, acc[0][2]);
            acc[0][3] = fma2(wB.y, xd0, acc[0][3]);
            acc[1][0] = fma2(wA.x, xd1, acc[1][0]);
            acc[1][1] = fma2(wA.y, xd1, acc[1][1]);
            acc[1][2] = fma2(wB.x, xd1, acc[1][2]);
            acc[1][3] = fma2(wB.y, xd1, acc[1][3]);
            acc[2][0] = fma2(wA.x, xd2, acc[2][0]);
            acc[2][1] = fma2(wA.y, xd2, acc[2][1]);
            acc[2][2] = fma2(wB.x, xd2, acc[2][2]);
            acc[2][3] = fma2(wB.y, xd2, acc[2][3]);
            acc[3][0] = fma2(wA.x, xd3, acc[3][0]);
            acc[3][1] = fma2(wA.y, xd3, acc[3][1]);
            acc[3][2] = fma2(wB.x, xd3, acc[3][2]);
            acc[3][3] = fma2(wB.y, xd3, acc[3][3]);
        }
    }
    __syncthreads();

    // ---- GELU(exact) + write Hs (transposed) ; load W2 into Ws ----
    for (int idx = t; idx < 9216; idx += 192) Ws[idx] = W2[idx];
    float* Hs = Xs;
#pragma unroll
    for (int r = 0; r < 4; ++r)
#pragma unroll
        for (int p = 0; p < 4; ++p) {
            float2 v = unpack2(acc[r][p]);
            int j = j0 + 2 * p;
            float a0 = v.x + b1[j];
            float a1 = v.y + b1[j + 1];
            a0 = 0.5f * a0 * (1.0f + erff(a0 * 0.7071067811865476f));
            a1 = 0.5f * a1 * (1.0f + erff(a1 * 0.7071067811865476f));
            Hs[(size_t)j       * 68 + r0 + r] = a0;
            Hs[(size_t)(j + 1) * 68 + r0 + r] = a1;
        }
    __syncthreads();

    // ---- phase 2: mix = hid @ W2 ----
    ull acc2[4][4];
#pragma unroll
    for (int r = 0; r < 4; ++r)
#pragma unroll
        for (int p = 0; p < 4; ++p) acc2[r][p] = 0ull;
#pragma unroll 4
    for (int i = 0; i < 96; ++i) {
        const ulonglong2 wA = *(const ulonglong2*)&Ws[i * 96 + j0];
        const ulonglong2 wB = *(const ulonglong2*)&Ws[i * 96 + j0 + 4];
        const float4 hv = *(const float4*)&Hs[i * 68 + r0];
        ull xd0 = pack2(hv.x, hv.x), xd1 = pack2(hv.y, hv.y);
        ull xd2 = pack2(hv.z, hv.z), xd3 = pack2(hv.w, hv.w);
        acc2[0][0] = fma2(wA.x, xd0, acc2[0][0]);
        acc2[0][1] = fma2(wA.y, xd0, acc2[0][1]);
        acc2[0][2] = fma2(wB.x, xd0, acc2[0][2]);
        acc2[0][3] = fma2(wB.y, xd0, acc2[0][3]);
        acc2[1][0] = fma2(wA.x, xd1, acc2[1][0]);
        acc2[1][1] = fma2(wA.y, xd1, acc2[1][1]);
        acc2[1][2] = fma2(wB.x, xd1, acc2[1][2]);
        acc2[1][3] = fma2(wB.y, xd1, acc2[1][3]);
        acc2[2][0] = fma2(wA.x, xd2, acc2[2][0]);
        acc2[2][1] = fma2(wA.y, xd2, acc2[2][1]);
        acc2[2][2] = fma2(wB.x, xd2, acc2[2][2]);
        acc2[2][3] = fma2(wB.y, xd2, acc2[2][3]);
        acc2[3][0] = fma2(wA.x, xd3, acc2[3][0]);
        acc2[3][1] = fma2(wA.y, xd3, acc2[3][1]);
        acc2[3][2] = fma2(wB.x, xd3, acc2[3][2]);
        acc2[3][3] = fma2(wB.y, xd3, acc2[3][3]);
    }
    __syncthreads();

    // ---- + b2, stage to Ms, softmax over k ----
    float* Ms = Ws;
#pragma unroll
    for (int r = 0; r < 4; ++r)
#pragma unroll
        for (int p = 0; p < 4; ++p) {
            float2 v = unpack2(acc2[r][p]);
            int j = j0 + 2 * p;
            Ms[(r0 + r) * 96 + j]     = v.x + b2[j];
            Ms[(r0 + r) * 96 + j + 1] = v.y + b2[j + 1];
        }
    __syncthreads();

    for (int g = t; g < 384; g += 192) {
        int r = g / 6, h = g % 6;
        float vals[Kk];
        float vmax = -1e30f;
#pragma unroll
        for (int k = 0; k < Kk; ++k) {
            vals[k] = Ms[r * 96 + k * Hh + h];
            vmax = fmaxf(vmax, vals[k]);
        }
        float s = 0.f;
#pragma unroll
        for (int k = 0; k < Kk; ++k) { vals[k] = __expf(vals[k] - vmax); s += vals[k]; }
        float inv = 1.0f / s;
        size_t base = ((size_t)(row0 + r) * Hh + h) * Kk;
#pragma unroll
        for (int k = 0; k < Kk; ++k) g_mix[base + k] = vals[k] * inv;
    }
}

// ---------------------------------------------------------------------------
// Kernel 3: fused mixer v2 — n chunked by 28, all phase-2 operands in smem.
// Block = (m-tile mt of 14, batch b), 384 threads, 2 CTAs/SM.
// per chunk c (n0 = 28c):
//   stage xs[28][384]           (coalesced float4 from x[b])
//   stage wb_s[28][14][16]      (from g_wbt, k-contiguous)
//   phase1: ws[nl][h][16(m pad)] = sum_k mix[b,n,h,k] * wb_s[nl][ml][k]
//   phase2: acc[7 f32x2 pairs over 14 m] += ws row * xs[nl][t]
// smem = 10752 + 6272 + 2688 floats = 78848 B
// ---------------------------------------------------------------------------
#define MX_XS   10752
#define MX_WB   6272
#define MX_WS   2688
#define MX_SMEM_FLOATS (MX_XS + MX_WB + MX_WS)

extern "C" __global__ void __launch_bounds__(384, 2)
mixer_kernel(const float* __restrict__ x, float* __restrict__ out) {
    extern __shared__ float sm[];
    float* xs   = sm;                  // [nl][384]
    float* wb_s = sm + MX_XS;          // [nl][ml][16]
    float* ws   = sm + MX_XS + MX_WB;  // [nl][h][16]

    const int t  = threadIdx.x;
    const int b  = blockIdx.y;
    const int mt = blockIdx.x;    // 0..13
    const int h  = t >> 6;

    ull acc[7];
#pragma unroll
    for (int q = 0; q < 7; ++q) acc[q] = 0ull;

    for (int c = 0; c < NCH; ++c) {
        const int n0 = c * CH;
        __syncthreads();
        // stage x chunk: 28*384 floats = 2688 float4, 7 per thread
        {
            const float4* src = (const float4*)(x + ((size_t)b * Nn + n0) * DIMc);
            float4* dst = (float4*)xs;
#pragma unroll
            for (int i = 0; i < 7; ++i) dst[t + i * 384] = src[t + i * 384];
        }
        // stage wbt chunk: 28*14*16 floats = 1568 float4
        {
            const float4* src = (const float4*)g_wbt;
            float4* dst = (float4*)wb_s;
            for (int idx = t; idx < 1568; idx += 384) {
                int pos = idx >> 2, q = idx & 3;
                int nl = pos / TM, ml = pos - nl * TM;
                dst[idx] = src[(((n0 + nl) * Nn + mt * TM + ml) << 2) + q];
            }
        }
        __syncthreads();
        // phase 1: 336 active threads; each handles (nl, hh) for 7 m's
        if (t < 336) {
            int nl = t / 12, sub = t - nl * 12;
            int hh = sub >> 1, m0 = (sub & 1) * 7;
            const float4* mx = (const float4*)&g_mix[(((size_t)b * Nn + n0 + nl) * Hh + hh) * Kk];
            float4 a0 = mx[0], a1 = mx[1], a2 = mx[2], a3 = mx[3];
#pragma unroll
            for (int ml = m0; ml < m0 + 7; ++ml) {
                const float4* wv = (const float4*)&wb_s[(nl * TM + ml) * Kk];
                float4 w0 = wv[0], w1 = wv[1], w2 = wv[2], w3 = wv[3];
                float s = w0.x * a0.x;
                s = fmaf(w0.y, a0.y, s); s = fmaf(w0.z, a0.z, s); s = fmaf(w0.w, a0.w, s);
                s = fmaf(w1.x, a1.x, s); s = fmaf(w1.y, a1.y, s); s = fmaf(w1.z, a1.z, s); s = fmaf(w1.w, a1.w, s);
                s = fmaf(w2.x, a2.x, s); s = fmaf(w2.y, a2.y, s); s = fmaf(w2.z, a2.z, s); s = fmaf(w2.w, a2.w, s);
                s = fmaf(w3.x, a3.x, s); s = fmaf(w3.y, a3.y, s); s = fmaf(w3.z, a3.z, s); s = fmaf(w3.w, a3.w, s);
                ws[(nl * Hh + hh) * 16 + ml] = s;
            }
        }
        __syncthreads();
        // phase 2: all operands in smem
#pragma unroll 4
        for (int nl = 0; nl < CH; ++nl) {
            float xv = xs[nl * 384 + t];
            ull xx = pack2(xv, xv);
            const float* wr = &ws[(nl * Hh + h) * 16];
            ulonglong2 wA = *(const ulonglong2*)&wr[0];
            ulonglong2 wB = *(const ulonglong2*)&wr[4];
            ulonglong2 wC = *(const ulonglong2*)&wr[8];
            ull        wD = *(const ull*)&wr[12];
            acc[0] = fma2(wA.x, xx, acc[0]);
            acc[1] = fma2(wA.y, xx, acc[1]);
            acc[2] = fma2(wB.x, xx, acc[2]);
            acc[3] = fma2(wB.y, xx, acc[3]);
            acc[4] = fma2(wC.x, xx, acc[4]);
            acc[5] = fma2(wC.y, xx, acc[5]);
            acc[6] = fma2(wD,   xx, acc[6]);
        }
    }

    float* ob = out + ((size_t)b * Nn + mt * TM) * DIMc + t;
#pragma unroll
    for (int q = 0; q < 7; ++q) {
        float2 v = unpack2(acc[q]);
        ob[(size_t)(2 * q)     * DIMc] = v.x;
        ob[(size_t)(2 * q + 1) * DIMc] = v.y;
    }
}

// ---------------------------------------------------------------------------
extern "C" void kernel_launch(void* const* d_in, const int* in_sizes, int n_in,
                              void* d_out, int out_size) {
    const float* x  = (const float*)d_in[0];
    const float* W1 = (const float*)d_in[1];
    const float* b1 = (const float*)d_in[2];
    const float* W2 = (const float*)d_in[3];
    const float* b2 = (const float*)d_in[4];
    const float* wb = (const float*)d_in[5];
    float* out = (float*)d_out;

    cudaFuncSetAttribute((const void*)adapter_kernel,
                         cudaFuncAttributeMaxDynamicSharedMemorySize,
                         AD_SMEM_FLOATS * 4);
    cudaFuncSetAttribute((const void*)mixer_kernel,
                         cudaFuncAttributeMaxDynamicSharedMemorySize,
                         MX_SMEM_FLOATS * 4);

    // Order: adapter, transpose, mixer — so ncu's skip-5 capture lands on the
    // mixer (launch index 5) while preserving dependencies (stream-ordered).
    adapter_kernel<<<392, 192, AD_SMEM_FLOATS * 4>>>(x, W1, b1, W2, b2);
    transpose_wb_kernel<<<(Nn * Nn + 255) / 256, 256>>>(wb);
    mixer_kernel<<<dim3(TM, Bz), 384, MX_SMEM_FLOATS * 4>>>(x, out);
}

// round 5
// speedup vs baseline: 1.5372x; 1.0017x over previous
#include <cuda_runtime.h>
#include <cstdint>

#define Bz   128
#define Nn   196
#define DIMc 384
#define Kk   16
#define Hh   6
#define HD   64
#define DR   96
#define TM   14   // m-tile width; 14*14 == 196
#define CH   28   // n-chunk in mixer; 7*28 == 196
#define NCH  7

// Scratch (device globals — allocation-free)
__device__ __align__(16) float g_wbt[(size_t)Nn * Nn * Kk];      // [n][m][k]
__device__ __align__(16) float g_mix[(size_t)Bz * Nn * Hh * Kk]; // [b][n][h][k]

typedef unsigned long long ull;

__device__ __forceinline__ ull fma2(ull a, ull b, ull c) {
    ull d;
    asm("fma.rn.f32x2 %0, %1, %2, %3;" : "=l"(d) : "l"(a), "l"(b), "l"(c));
    return d;
}
__device__ __forceinline__ ull pack2(float lo, float hi) {
    ull d;
    asm("mov.b64 %0, {%1, %2};" : "=l"(d) : "r"(__float_as_uint(lo)), "r"(__float_as_uint(hi)));
    return d;
}
__device__ __forceinline__ float2 unpack2(ull v) {
    unsigned lo, hi;
    asm("mov.b64 {%0, %1}, %2;" : "=r"(lo), "=r"(hi) : "l"(v));
    return make_float2(__uint_as_float(lo), __uint_as_float(hi));
}

// ---------------------------------------------------------------------------
// Kernel 1: weight_bank [k][n][m] -> g_wbt [n][m][k]  (k contiguous)
// ---------------------------------------------------------------------------
extern "C" __global__ void transpose_wb_kernel(const float* __restrict__ wb) {
    int t = blockIdx.x * 256 + threadIdx.x;
    if (t >= Nn * Nn) return;
    int n = t / Nn, m = t % Nn;
    float v[Kk];
#pragma unroll
    for (int k = 0; k < Kk; ++k)
        v[k] = wb[((size_t)k * Nn + n) * Nn + m];   // coalesced over m
    float4* dst = (float4*)&g_wbt[(size_t)t * Kk];
    dst[0] = make_float4(v[0],  v[1],  v[2],  v[3]);
    dst[1] = make_float4(v[4],  v[5],  v[6],  v[7]);
    dst[2] = make_float4(v[8],  v[9],  v[10], v[11]);
    dst[3] = make_float4(v[12], v[13], v[14], v[15]);
}

// ---------------------------------------------------------------------------
// Kernel 2: adapter.  64 rows/block, 192 threads (12 colgroups x 16 rowgroups)
// hid = gelu(x@W1+b1); mix = hid@W2+b2; softmax over k; -> g_mix[b][n][h][k]
// ---------------------------------------------------------------------------
#define AD_SMEM_FLOATS (9216 + 96*68)

extern "C" __global__ void __launch_bounds__(192)
adapter_kernel(const float* __restrict__ x,
               const float* __restrict__ W1, const float* __restrict__ b1,
               const float* __restrict__ W2, const float* __restrict__ b2) {
    extern __shared__ float sm[];
    float* Ws = sm;            // 9216 floats (96x96)
    float* Xs = sm + 9216;     // 96 x 68 (padded), reused as Hs

    const int t   = threadIdx.x;
    const int tc  = t % 12;           // col group
    const int rg  = t / 12;           // row group
    const int j0  = tc * 8;
    const int r0  = rg * 4;
    const int row0 = blockIdx.x * 64; // 392 blocks * 64 = 25088 rows

    ull acc[4][4];
#pragma unroll
    for (int r = 0; r < 4; ++r)
#pragma unroll
        for (int p = 0; p < 4; ++p) acc[r][p] = 0ull;

    // ---- phase 1: hid = x @ W1 over 4 i-tiles of 96 ----
    for (int it = 0; it < 4; ++it) {
        __syncthreads();
        for (int idx = t; idx < 9216; idx += 192)
            Ws[idx] = W1[(size_t)it * 96 * 96 + idx];
        for (int idx = t; idx < 6144; idx += 192) {
            int il = idx % 96, r = idx / 96;
            Xs[il * 68 + r] = x[(size_t)(row0 + r) * DIMc + it * 96 + il];
        }
        __syncthreads();
#pragma unroll 4
        for (int il = 0; il < 96; ++il) {
            const ulonglong2 wA = *(const ulonglong2*)&Ws[il * 96 + j0];
            const ulonglong2 wB = *(const ulonglong2*)&Ws[il * 96 + j0 + 4];
            const float4 xv = *(const float4*)&Xs[il * 68 + r0];
            ull xd0 = pack2(xv.x, xv.x), xd1 = pack2(xv.y, xv.y);
            ull xd2 = pack2(xv.z, xv.z), xd3 = pack2(xv.w, xv.w);
            acc[0][0] = fma2(wA.x, xd0, acc[0][0]);
            acc[0][1] = fma2(wA.y, xd0, acc[0][1]);
            acc[0][2] = fma2(wB.x, xd0, acc[0][2]);
            acc[0][3] = fma2(wB.y, xd0, acc[0][3]);
            acc[1][0] = fma2(wA.x, xd1, acc[1][0]);
            acc[1][1] = fma2(wA.y, xd1, acc[1][1]);
            acc[1][2] = fma2(wB.x, xd1, acc[1][2]);
            acc[1][3] = fma2(wB.y, xd1, acc[1][3]);
            acc[2][0] = fma2(wA.x, xd2, acc[2][0]);
            acc[2][1] = fma2(wA.y, xd2, acc[2][1]);
            acc[2][2] = fma2(wB.x, xd2, acc[2][2]);
            acc[2][3] = fma2(wB.y, xd2, acc[2][3]);
            acc[3][0] = fma2(wA.x, xd3, acc[3][0]);
            acc[3][1] = fma2(wA.y, xd3, acc[3][1]);
            acc[3][2] = fma2(wB.x, xd3, acc[3][2]);
            acc[3][3] = fma2(wB.y, xd3, acc[3][3]);
        }
    }
    __syncthreads();

    // ---- GELU(exact) + write Hs (transposed) ; load W2 into Ws ----
    for (int idx = t; idx < 9216; idx += 192) Ws[idx] = W2[idx];
    float* Hs = Xs;
#pragma unroll
    for (int r = 0; r < 4; ++r)
#pragma unroll
        for (int p = 0; p < 4; ++p) {
            float2 v = unpack2(acc[r][p]);
            int j = j0 + 2 * p;
            float a0 = v.x + b1[j];
            float a1 = v.y + b1[j + 1];
            a0 = 0.5f * a0 * (1.0f + erff(a0 * 0.7071067811865476f));
            a1 = 0.5f * a1 * (1.0f + erff(a1 * 0.7071067811865476f));
            Hs[(size_t)j       * 68 + r0 + r] = a0;
            Hs[(size_t)(j + 1) * 68 + r0 + r] = a1;
        }
    __syncthreads();

    // ---- phase 2: mix = hid @ W2 ----
    ull acc2[4][4];
#pragma unroll
    for (int r = 0; r < 4; ++r)
#pragma unroll
        for (int p = 0; p < 4; ++p) acc2[r][p] = 0ull;
#pragma unroll 4
    for (int i = 0; i < 96; ++i) {
        const ulonglong2 wA = *(const ulonglong2*)&Ws[i * 96 + j0];
        const ulonglong2 wB = *(const ulonglong2*)&Ws[i * 96 + j0 + 4];
        const float4 hv = *(const float4*)&Hs[i * 68 + r0];
        ull xd0 = pack2(hv.x, hv.x), xd1 = pack2(hv.y, hv.y);
        ull xd2 = pack2(hv.z, hv.z), xd3 = pack2(hv.w, hv.w);
        acc2[0][0] = fma2(wA.x, xd0, acc2[0][0]);
        acc2[0][1] = fma2(wA.y, xd0, acc2[0][1]);
        acc2[0][2] = fma2(wB.x, xd0, acc2[0][2]);
        acc2[0][3] = fma2(wB.y, xd0, acc2[0][3]);
        acc2[1][0] = fma2(wA.x, xd1, acc2[1][0]);
        acc2[1][1] = fma2(wA.y, xd1, acc2[1][1]);
        acc2[1][2] = fma2(wB.x, xd1, acc2[1][2]);
        acc2[1][3] = fma2(wB.y, xd1, acc2[1][3]);
        acc2[2][0] = fma2(wA.x, xd2, acc2[2][0]);
        acc2[2][1] = fma2(wA.y, xd2, acc2[2][1]);
        acc2[2][2] = fma2(wB.x, xd2, acc2[2][2]);
        acc2[2][3] = fma2(wB.y, xd2, acc2[2][3]);
        acc2[3][0] = fma2(wA.x, xd3, acc2[3][0]);
        acc2[3][1] = fma2(wA.y, xd3, acc2[3][1]);
        acc2[3][2] = fma2(wB.x, xd3, acc2[3][2]);
        acc2[3][3] = fma2(wB.y, xd3, acc2[3][3]);
    }
    __syncthreads();

    // ---- + b2, stage to Ms, softmax over k ----
    float* Ms = Ws;
#pragma unroll
    for (int r = 0; r < 4; ++r)
#pragma unroll
        for (int p = 0; p < 4; ++p) {
            float2 v = unpack2(acc2[r][p]);
            int j = j0 + 2 * p;
            Ms[(r0 + r) * 96 + j]     = v.x + b2[j];
            Ms[(r0 + r) * 96 + j + 1] = v.y + b2[j + 1];
        }
    __syncthreads();

    for (int g = t; g < 384; g += 192) {
        int r = g / 6, h = g % 6;
        float vals[Kk];
        float vmax = -1e30f;
#pragma unroll
        for (int k = 0; k < Kk; ++k) {
            vals[k] = Ms[r * 96 + k * Hh + h];
            vmax = fmaxf(vmax, vals[k]);
        }
        float s = 0.f;
#pragma unroll
        for (int k = 0; k < Kk; ++k) { vals[k] = __expf(vals[k] - vmax); s += vals[k]; }
        float inv = 1.0f / s;
        size_t base = ((size_t)(row0 + r) * Hh + h) * Kk;
#pragma unroll
        for (int k = 0; k < Kk; ++k) g_mix[base + k] = vals[k] * inv;
    }
}

// ---------------------------------------------------------------------------
// Kernel 3: fused mixer v2 — n chunked by 28, all phase-2 operands in smem.
// Block = (m-tile mt of 14, batch b), 384 threads, 2 CTAs/SM.
// per chunk c (n0 = 28c):
//   stage xs[28][384]           (coalesced float4 from x[b])
//   stage wb_s[28][14][16]      (from g_wbt, k-contiguous)
//   phase1: ws[nl][h][16(m pad)] = sum_k mix[b,n,h,k] * wb_s[nl][ml][k]
//   phase2: acc[7 f32x2 pairs over 14 m] += ws row * xs[nl][t]
// smem = 10752 + 6272 + 2688 floats = 78848 B
// ---------------------------------------------------------------------------
#define MX_XS   10752
#define MX_WB   6272
#define MX_WS   2688
#define MX_SMEM_FLOATS (MX_XS + MX_WB + MX_WS)

extern "C" __global__ void __launch_bounds__(384, 2)
mixer_kernel(const float* __restrict__ x, float* __restrict__ out) {
    extern __shared__ float sm[];
    float* xs   = sm;                  // [nl][384]
    float* wb_s = sm + MX_XS;          // [nl][ml][16]
    float* ws   = sm + MX_XS + MX_WB;  // [nl][h][16]

    const int t  = threadIdx.x;
    const int b  = blockIdx.y;
    const int mt = blockIdx.x;    // 0..13
    const int h  = t >> 6;

    ull acc[7];
#pragma unroll
    for (int q = 0; q < 7; ++q) acc[q] = 0ull;

    for (int c = 0; c < NCH; ++c) {
        const int n0 = c * CH;
        __syncthreads();
        // stage x chunk: 28*384 floats = 2688 float4, 7 per thread
        {
            const float4* src = (const float4*)(x + ((size_t)b * Nn + n0) * DIMc);
            float4* dst = (float4*)xs;
#pragma unroll
            for (int i = 0; i < 7; ++i) dst[t + i * 384] = src[t + i * 384];
        }
        // stage wbt chunk: 28*14*16 floats = 1568 float4
        {
            const float4* src = (const float4*)g_wbt;
            float4* dst = (float4*)wb_s;
            for (int idx = t; idx < 1568; idx += 384) {
                int pos = idx >> 2, q = idx & 3;
                int nl = pos / TM, ml = pos - nl * TM;
                dst[idx] = src[(((n0 + nl) * Nn + mt * TM + ml) << 2) + q];
            }
        }
        __syncthreads();
        // phase 1: 336 active threads; each handles (nl, hh) for 7 m's
        if (t < 336) {
            int nl = t / 12, sub = t - nl * 12;
            int hh = sub >> 1, m0 = (sub & 1) * 7;
            const float4* mx = (const float4*)&g_mix[(((size_t)b * Nn + n0 + nl) * Hh + hh) * Kk];
            float4 a0 = mx[0], a1 = mx[1], a2 = mx[2], a3 = mx[3];
#pragma unroll
            for (int ml = m0; ml < m0 + 7; ++ml) {
                const float4* wv = (const float4*)&wb_s[(nl * TM + ml) * Kk];
                float4 w0 = wv[0], w1 = wv[1], w2 = wv[2], w3 = wv[3];
                float s = w0.x * a0.x;
                s = fmaf(w0.y, a0.y, s); s = fmaf(w0.z, a0.z, s); s = fmaf(w0.w, a0.w, s);
                s = fmaf(w1.x, a1.x, s); s = fmaf(w1.y, a1.y, s); s = fmaf(w1.z, a1.z, s); s = fmaf(w1.w, a1.w, s);
                s = fmaf(w2.x, a2.x, s); s = fmaf(w2.y, a2.y, s); s = fmaf(w2.z, a2.z, s); s = fmaf(w2.w, a2.w, s);
                s = fmaf(w3.x, a3.x, s); s = fmaf(w3.y, a3.y, s); s = fmaf(w3.z, a3.z, s); s = fmaf(w3.w, a3.w, s);
                ws[(nl * Hh + hh) * 16 + ml] = s;
            }
        }
        __syncthreads();
        // phase 2: all operands in smem
#pragma unroll 4
        for (int nl = 0; nl < CH; ++nl) {
            float xv = xs[nl * 384 + t];
            ull xx = pack2(xv, xv);
            const float* wr = &ws[(nl * Hh + h) * 16];
            ulonglong2 wA = *(const ulonglong2*)&wr[0];
            ulonglong2 wB = *(const ulonglong2*)&wr[4];
            ulonglong2 wC = *(const ulonglong2*)&wr[8];
            ull        wD = *(const ull*)&wr[12];
            acc[0] = fma2(wA.x, xx, acc[0]);
            acc[1] = fma2(wA.y, xx, acc[1]);
            acc[2] = fma2(wB.x, xx, acc[2]);
            acc[3] = fma2(wB.y, xx, acc[3]);
            acc[4] = fma2(wC.x, xx, acc[4]);
            acc[5] = fma2(wC.y, xx, acc[5]);
            acc[6] = fma2(wD,   xx, acc[6]);
        }
    }

    float* ob = out + ((size_t)b * Nn + mt * TM) * DIMc + t;
#pragma unroll
    for (int q = 0; q < 7; ++q) {
        float2 v = unpack2(acc[q]);
        ob[(size_t)(2 * q)     * DIMc] = v.x;
        ob[(size_t)(2 * q + 1) * DIMc] = v.y;
    }
}

// ---------------------------------------------------------------------------
extern "C" void kernel_launch(void* const* d_in, const int* in_sizes, int n_in,
                              void* d_out, int out_size) {
    const float* x  = (const float*)d_in[0];
    const float* W1 = (const float*)d_in[1];
    const float* b1 = (const float*)d_in[2];
    const float* W2 = (const float*)d_in[3];
    const float* b2 = (const float*)d_in[4];
    const float* wb = (const float*)d_in[5];
    float* out = (float*)d_out;

    cudaFuncSetAttribute((const void*)adapter_kernel,
                         cudaFuncAttributeMaxDynamicSharedMemorySize,
                         AD_SMEM_FLOATS * 4);
    cudaFuncSetAttribute((const void*)mixer_kernel,
                         cudaFuncAttributeMaxDynamicSharedMemorySize,
                         MX_SMEM_FLOATS * 4);

    // Order: adapter, transpose, mixer — so ncu's skip-5 capture lands on the
    // mixer (launch index 5) while preserving dependencies (stream-ordered).
    adapter_kernel<<<392, 192, AD_SMEM_FLOATS * 4>>>(x, W1, b1, W2, b2);
    transpose_wb_kernel<<<(Nn * Nn + 255) / 256, 256>>>(wb);
    mixer_kernel<<<dim3(TM, Bz), 384, MX_SMEM_FLOATS * 4>>>(x, out);
}

// round 6
// speedup vs baseline: 1.6668x; 1.0843x over previous
#include <cuda_runtime.h>
#include <cstdint>

#define Bz   128
#define Nn   196
#define DIMc 384
#define Kk   16
#define Hh   6
#define HD   64
#define DR   96
#define TMX  28   // mixer m-tile width; 7*28 == 196
#define CH   28   // mixer n-chunk; 7*28 == 196
#define NCH  7

// Scratch (device globals — allocation-free)
__device__ __align__(16) float g_wbt[(size_t)Nn * Nn * Kk];      // [n][m][k]
__device__ __align__(16) float g_mix[(size_t)Bz * Nn * Hh * Kk]; // [b][n][h][k]

typedef unsigned long long ull;

__device__ __forceinline__ ull fma2(ull a, ull b, ull c) {
    ull d;
    asm("fma.rn.f32x2 %0, %1, %2, %3;" : "=l"(d) : "l"(a), "l"(b), "l"(c));
    return d;
}
__device__ __forceinline__ ull pack2(float lo, float hi) {
    ull d;
    asm("mov.b64 %0, {%1, %2};" : "=l"(d) : "r"(__float_as_uint(lo)), "r"(__float_as_uint(hi)));
    return d;
}
__device__ __forceinline__ float2 unpack2(ull v) {
    unsigned lo, hi;
    asm("mov.b64 {%0, %1}, %2;" : "=r"(lo), "=r"(hi) : "l"(v));
    return make_float2(__uint_as_float(lo), __uint_as_float(hi));
}

// ---------------------------------------------------------------------------
// Kernel 1: weight_bank [k][n][m] -> g_wbt [n][m][k]  (k contiguous)
// ---------------------------------------------------------------------------
extern "C" __global__ void transpose_wb_kernel(const float* __restrict__ wb) {
    int t = blockIdx.x * 256 + threadIdx.x;
    if (t >= Nn * Nn) return;
    int n = t / Nn, m = t % Nn;
    float v[Kk];
#pragma unroll
    for (int k = 0; k < Kk; ++k)
        v[k] = wb[((size_t)k * Nn + n) * Nn + m];   // coalesced over m
    float4* dst = (float4*)&g_wbt[(size_t)t * Kk];
    dst[0] = make_float4(v[0],  v[1],  v[2],  v[3]);
    dst[1] = make_float4(v[4],  v[5],  v[6],  v[7]);
    dst[2] = make_float4(v[8],  v[9],  v[10], v[11]);
    dst[3] = make_float4(v[12], v[13], v[14], v[15]);
}

// ---------------------------------------------------------------------------
// Kernel 2: adapter v2 — duplicated-X smem layout.
// Xs2/Hs2 store each value as (v,v) so the broadcast operand of fma.rn.f32x2
// is a single LDS.64 (no pack MOVs). Stride 130 floats/row to avoid bank
// conflicts (il*130 + 2r).
// smem: Ws 9216 + Xs2 96*130=12480 floats = 86784 B
// ---------------------------------------------------------------------------
#define XD 130
#define AD_SMEM_FLOATS (9216 + 96*XD)

extern "C" __global__ void __launch_bounds__(192)
adapter_kernel(const float* __restrict__ x,
               const float* __restrict__ W1, const float* __restrict__ b1,
               const float* __restrict__ W2, const float* __restrict__ b2) {
    extern __shared__ float sm[];
    float* Ws  = sm;            // 9216 floats (96x96)
    float* Xs2 = sm + 9216;     // [il][r] duplicated pairs, stride XD

    const int t   = threadIdx.x;
    const int tc  = t % 12;           // col group
    const int rg  = t / 12;           // row group
    const int j0  = tc * 8;
    const int r0  = rg * 4;
    const int row0 = blockIdx.x * 64; // 392 blocks * 64 = 25088 rows

    ull acc[4][4];
#pragma unroll
    for (int r = 0; r < 4; ++r)
#pragma unroll
        for (int p = 0; p < 4; ++p) acc[r][p] = 0ull;

    // ---- phase 1: hid = x @ W1 over 4 i-tiles of 96 ----
    for (int it = 0; it < 4; ++it) {
        __syncthreads();
        for (int idx = t; idx < 9216; idx += 192)
            Ws[idx] = W1[(size_t)it * 96 * 96 + idx];
        for (int idx = t; idx < 6144; idx += 192) {
            int il = idx % 96, r = idx / 96;
            float v = x[(size_t)(row0 + r) * DIMc + it * 96 + il];
            *(float2*)&Xs2[il * XD + 2 * r] = make_float2(v, v);
        }
        __syncthreads();
#pragma unroll 4
        for (int il = 0; il < 96; ++il) {
            const ulonglong2 wA = *(const ulonglong2*)&Ws[il * 96 + j0];
            const ulonglong2 wB = *(const ulonglong2*)&Ws[il * 96 + j0 + 4];
            const float* xr = &Xs2[il * XD + 2 * r0];
            ull xd0 = *(const ull*)&xr[0];
            ull xd1 = *(const ull*)&xr[2];
            ull xd2 = *(const ull*)&xr[4];
            ull xd3 = *(const ull*)&xr[6];
            acc[0][0] = fma2(wA.x, xd0, acc[0][0]);
            acc[0][1] = fma2(wA.y, xd0, acc[0][1]);
            acc[0][2] = fma2(wB.x, xd0, acc[0][2]);
            acc[0][3] = fma2(wB.y, xd0, acc[0][3]);
            acc[1][0] = fma2(wA.x, xd1, acc[1][0]);
            acc[1][1] = fma2(wA.y, xd1, acc[1][1]);
            acc[1][2] = fma2(wB.x, xd1, acc[1][2]);
            acc[1][3] = fma2(wB.y, xd1, acc[1][3]);
            acc[2][0] = fma2(wA.x, xd2, acc[2][0]);
            acc[2][1] = fma2(wA.y, xd2, acc[2][1]);
            acc[2][2] = fma2(wB.x, xd2, acc[2][2]);
            acc[2][3] = fma2(wB.y, xd2, acc[2][3]);
            acc[3][0] = fma2(wA.x, xd3, acc[3][0]);
            acc[3][1] = fma2(wA.y, xd3, acc[3][1]);
            acc[3][2] = fma2(wB.x, xd3, acc[3][2]);
            acc[3][3] = fma2(wB.y, xd3, acc[3][3]);
        }
    }
    __syncthreads();

    // ---- GELU(exact) + write Hs2 (duplicated pairs) ; load W2 into Ws ----
    for (int idx = t; idx < 9216; idx += 192) Ws[idx] = W2[idx];
    float* Hs2 = Xs2;  // [i][r] duplicated, stride XD
#pragma unroll
    for (int r = 0; r < 4; ++r)
#pragma unroll
        for (int p = 0; p < 4; ++p) {
            float2 v = unpack2(acc[r][p]);
            int j = j0 + 2 * p;
            float a0 = v.x + b1[j];
            float a1 = v.y + b1[j + 1];
            a0 = 0.5f * a0 * (1.0f + erff(a0 * 0.7071067811865476f));
            a1 = 0.5f * a1 * (1.0f + erff(a1 * 0.7071067811865476f));
            *(float2*)&Hs2[(size_t)j       * XD + 2 * (r0 + r)] = make_float2(a0, a0);
            *(float2*)&Hs2[(size_t)(j + 1) * XD + 2 * (r0 + r)] = make_float2(a1, a1);
        }
    __syncthreads();

    // ---- phase 2: mix = hid @ W2 ----
    ull acc2[4][4];
#pragma unroll
    for (int r = 0; r < 4; ++r)
#pragma unroll
        for (int p = 0; p < 4; ++p) acc2[r][p] = 0ull;
#pragma unroll 4
    for (int i = 0; i < 96; ++i) {
        const ulonglong2 wA = *(const ulonglong2*)&Ws[i * 96 + j0];
        const ulonglong2 wB = *(const ulonglong2*)&Ws[i * 96 + j0 + 4];
        const float* hr = &Hs2[i * XD + 2 * r0];
        ull xd0 = *(const ull*)&hr[0];
        ull xd1 = *(const ull*)&hr[2];
        ull xd2 = *(const ull*)&hr[4];
        ull xd3 = *(const ull*)&hr[6];
        acc2[0][0] = fma2(wA.x, xd0, acc2[0][0]);
        acc2[0][1] = fma2(wA.y, xd0, acc2[0][1]);
        acc2[0][2] = fma2(wB.x, xd0, acc2[0][2]);
        acc2[0][3] = fma2(wB.y, xd0, acc2[0][3]);
        acc2[1][0] = fma2(wA.x, xd1, acc2[1][0]);
        acc2[1][1] = fma2(wA.y, xd1, acc2[1][1]);
        acc2[1][2] = fma2(wB.x, xd1, acc2[1][2]);
        acc2[1][3] = fma2(wB.y, xd1, acc2[1][3]);
        acc2[2][0] = fma2(wA.x, xd2, acc2[2][0]);
        acc2[2][1] = fma2(wA.y, xd2, acc2[2][1]);
        acc2[2][2] = fma2(wB.x, xd2, acc2[2][2]);
        acc2[2][3] = fma2(wB.y, xd2, acc2[2][3]);
        acc2[3][0] = fma2(wA.x, xd3, acc2[3][0]);
        acc2[3][1] = fma2(wA.y, xd3, acc2[3][1]);
        acc2[3][2] = fma2(wB.x, xd3, acc2[3][2]);
        acc2[3][3] = fma2(wB.y, xd3, acc2[3][3]);
    }
    __syncthreads();

    // ---- + b2, stage to Ms, softmax over k ----
    float* Ms = Ws;
#pragma unroll
    for (int r = 0; r < 4; ++r)
#pragma unroll
        for (int p = 0; p < 4; ++p) {
            float2 v = unpack2(acc2[r][p]);
            int j = j0 + 2 * p;
            Ms[(r0 + r) * 96 + j]     = v.x + b2[j];
            Ms[(r0 + r) * 96 + j + 1] = v.y + b2[j + 1];
        }
    __syncthreads();

    for (int g = t; g < 384; g += 192) {
        int r = g / 6, h = g % 6;
        float vals[Kk];
        float vmax = -1e30f;
#pragma unroll
        for (int k = 0; k < Kk; ++k) {
            vals[k] = Ms[r * 96 + k * Hh + h];
            vmax = fmaxf(vmax, vals[k]);
        }
        float s = 0.f;
#pragma unroll
        for (int k = 0; k < Kk; ++k) { vals[k] = __expf(vals[k] - vmax); s += vals[k]; }
        float inv = 1.0f / s;
        size_t base = ((size_t)(row0 + r) * Hh + h) * Kk;
#pragma unroll
        for (int k = 0; k < Kk; ++k) g_mix[base + k] = vals[k] * inv;
    }
}

// ---------------------------------------------------------------------------
// Kernel 3: fused mixer v3 — m-tile widened to 28 (grid 896), halving L2
// re-read traffic for x and mix. wbt is read straight from L2 in phase 1
// (4 independent LDG.128 per (n,m) — high MLP); mix chunk staged in smem.
//   per chunk c (n0 = 28c):
//     stage xs[28][384], mix_s[28][96]
//     phase1: ws[nl][h][32(m pad)] = sum_k mix_s[nl][h][k] * wbt[n0+nl][mg][k]
//     phase2: acc[14 f32x2 pairs over 28 m] += ws row * xs[nl][t]
// smem = 10752 + 2688 + 5376 floats = 75264 B; 2 CTAs/SM.
// ---------------------------------------------------------------------------
#define MX_XS   10752
#define MX_MIX  2688
#define MX_WS   5376
#define MX_SMEM_FLOATS (MX_XS + MX_MIX + MX_WS)

extern "C" __global__ void __launch_bounds__(384, 2)
mixer_kernel(const float* __restrict__ x, float* __restrict__ out) {
    extern __shared__ float sm[];
    float* xs    = sm;                     // [nl][384]
    float* mix_s = sm + MX_XS;             // [nl][96]  ([h][k] inner)
    float* ws    = sm + MX_XS + MX_MIX;    // [nl][h][32] (m padded 28->32)

    const int t  = threadIdx.x;
    const int b  = blockIdx.y;
    const int mt = blockIdx.x;    // 0..6
    const int h  = t >> 6;

    ull acc[14];
#pragma unroll
    for (int q = 0; q < 14; ++q) acc[q] = 0ull;

    for (int c = 0; c < NCH; ++c) {
        const int n0 = c * CH;
        __syncthreads();
        // stage x chunk: 28*384 floats = 2688 float4, 7 per thread
        {
            const float4* src = (const float4*)(x + ((size_t)b * Nn + n0) * DIMc);
            float4* dst = (float4*)xs;
#pragma unroll
            for (int i = 0; i < 7; ++i) dst[t + i * 384] = src[t + i * 384];
        }
        // stage mix chunk: 28*96 floats = 672 float4
        {
            const float4* src = (const float4*)&g_mix[((size_t)b * Nn + n0) * 96];
            float4* dst = (float4*)mix_s;
            for (int idx = t; idx < 672; idx += 384) dst[idx] = src[idx];
        }
        __syncthreads();
        // phase 1: 784 (nl, ml) pairs over 384 threads
        for (int p = t; p < CH * TMX; p += 384) {
            int nl = p / TMX, ml = p - nl * TMX;
            int mg = mt * TMX + ml;
            const float4* wv = (const float4*)&g_wbt[((size_t)(n0 + nl) * Nn + mg) * Kk];
            float4 w0 = __ldg(wv + 0), w1 = __ldg(wv + 1);
            float4 w2 = __ldg(wv + 2), w3 = __ldg(wv + 3);
#pragma unroll
            for (int hh = 0; hh < Hh; ++hh) {
                const float4* mx = (const float4*)&mix_s[nl * 96 + hh * Kk];
                float4 m0 = mx[0], m1 = mx[1], m2 = mx[2], m3 = mx[3];
                float s = w0.x * m0.x;
                s = fmaf(w0.y, m0.y, s); s = fmaf(w0.z, m0.z, s); s = fmaf(w0.w, m0.w, s);
                s = fmaf(w1.x, m1.x, s); s = fmaf(w1.y, m1.y, s); s = fmaf(w1.z, m1.z, s); s = fmaf(w1.w, m1.w, s);
                s = fmaf(w2.x, m2.x, s); s = fmaf(w2.y, m2.y, s); s = fmaf(w2.z, m2.z, s); s = fmaf(w2.w, m2.w, s);
                s = fmaf(w3.x, m3.x, s); s = fmaf(w3.y, m3.y, s); s = fmaf(w3.z, m3.z, s); s = fmaf(w3.w, m3.w, s);
                ws[(nl * Hh + hh) * 32 + ml] = s;
            }
        }
        __syncthreads();
        // phase 2: all operands in smem; 14 f32x2 accumulators over 28 m
#pragma unroll 4
        for (int nl = 0; nl < CH; ++nl) {
            float xv = xs[nl * 384 + t];
            ull xx = pack2(xv, xv);
            const float* wr = &ws[(nl * Hh + h) * 32];
            ulonglong2 wA = *(const ulonglong2*)&wr[0];
            ulonglong2 wB = *(const ulonglong2*)&wr[4];
            ulonglong2 wC = *(const ulonglong2*)&wr[8];
            ulonglong2 wD = *(const ulonglong2*)&wr[12];
            ulonglong2 wE = *(const ulonglong2*)&wr[16];
            ulonglong2 wF = *(const ulonglong2*)&wr[20];
            ulonglong2 wG = *(const ulonglong2*)&wr[24];
            acc[0]  = fma2(wA.x, xx, acc[0]);
            acc[1]  = fma2(wA.y, xx, acc[1]);
            acc[2]  = fma2(wB.x, xx, acc[2]);
            acc[3]  = fma2(wB.y, xx, acc[3]);
            acc[4]  = fma2(wC.x, xx, acc[4]);
            acc[5]  = fma2(wC.y, xx, acc[5]);
            acc[6]  = fma2(wD.x, xx, acc[6]);
            acc[7]  = fma2(wD.y, xx, acc[7]);
            acc[8]  = fma2(wE.x, xx, acc[8]);
            acc[9]  = fma2(wE.y, xx, acc[9]);
            acc[10] = fma2(wF.x, xx, acc[10]);
            acc[11] = fma2(wF.y, xx, acc[11]);
            acc[12] = fma2(wG.x, xx, acc[12]);
            acc[13] = fma2(wG.y, xx, acc[13]);
        }
    }

    float* ob = out + ((size_t)b * Nn + mt * TMX) * DIMc + t;
#pragma unroll
    for (int q = 0; q < 14; ++q) {
        float2 v = unpack2(acc[q]);
        ob[(size_t)(2 * q)     * DIMc] = v.x;
        ob[(size_t)(2 * q + 1) * DIMc] = v.y;
    }
}

// ---------------------------------------------------------------------------
extern "C" void kernel_launch(void* const* d_in, const int* in_sizes, int n_in,
                              void* d_out, int out_size) {
    const float* x  = (const float*)d_in[0];
    const float* W1 = (const float*)d_in[1];
    const float* b1 = (const float*)d_in[2];
    const float* W2 = (const float*)d_in[3];
    const float* b2 = (const float*)d_in[4];
    const float* wb = (const float*)d_in[5];
    float* out = (float*)d_out;

    cudaFuncSetAttribute((const void*)adapter_kernel,
                         cudaFuncAttributeMaxDynamicSharedMemorySize,
                         AD_SMEM_FLOATS * 4);
    cudaFuncSetAttribute((const void*)mixer_kernel,
                         cudaFuncAttributeMaxDynamicSharedMemorySize,
                         MX_SMEM_FLOATS * 4);

    adapter_kernel<<<392, 192, AD_SMEM_FLOATS * 4>>>(x, W1, b1, W2, b2);
    transpose_wb_kernel<<<(Nn * Nn + 255) / 256, 256>>>(wb);
    mixer_kernel<<<dim3(NCH, Bz), 384, MX_SMEM_FLOATS * 4>>>(x, out);
}

// round 7
// speedup vs baseline: 1.6839x; 1.0103x over previous
#include <cuda_runtime.h>
#include <cstdint>

#define Bz   128
#define Nn   196
#define DIMc 384
#define Kk   16
#define Hh   6
#define HD   64
#define DR   96
#define TMX  28   // mixer m-tile width; 7*28 == 196
#define CH   28   // mixer n-chunk; 7*28 == 196
#define NCH  7

// Scratch (device globals — allocation-free)
__device__ __align__(16) float g_wbt[(size_t)Nn * Nn * Kk];      // [n][m][k]
__device__ __align__(16) float g_mix[(size_t)Bz * Nn * Hh * Kk]; // [b][n][h][k]

typedef unsigned long long ull;

__device__ __forceinline__ ull fma2(ull a, ull b, ull c) {
    ull d;
    asm("fma.rn.f32x2 %0, %1, %2, %3;" : "=l"(d) : "l"(a), "l"(b), "l"(c));
    return d;
}
__device__ __forceinline__ ull pack2(float lo, float hi) {
    ull d;
    asm("mov.b64 %0, {%1, %2};" : "=l"(d) : "r"(__float_as_uint(lo)), "r"(__float_as_uint(hi)));
    return d;
}
__device__ __forceinline__ float2 unpack2(ull v) {
    unsigned lo, hi;
    asm("mov.b64 {%0, %1}, %2;" : "=r"(lo), "=r"(hi) : "l"(v));
    return make_float2(__uint_as_float(lo), __uint_as_float(hi));
}

// ---------------------------------------------------------------------------
// Kernel 1: weight_bank [k][n][m] -> g_wbt [n][m][k]  (k contiguous)
// ---------------------------------------------------------------------------
extern "C" __global__ void transpose_wb_kernel(const float* __restrict__ wb) {
    int t = blockIdx.x * 256 + threadIdx.x;
    if (t >= Nn * Nn) return;
    int n = t / Nn, m = t % Nn;
    float v[Kk];
#pragma unroll
    for (int k = 0; k < Kk; ++k)
        v[k] = wb[((size_t)k * Nn + n) * Nn + m];   // coalesced over m
    float4* dst = (float4*)&g_wbt[(size_t)t * Kk];
    dst[0] = make_float4(v[0],  v[1],  v[2],  v[3]);
    dst[1] = make_float4(v[4],  v[5],  v[6],  v[7]);
    dst[2] = make_float4(v[8],  v[9],  v[10], v[11]);
    dst[3] = make_float4(v[12], v[13], v[14], v[15]);
}

// ---------------------------------------------------------------------------
// Kernel 2: adapter v3 — NO W staging in smem (W1/W2 read via LDG, L1-hot and
// shared by all CTAs on an SM); only X lives in smem, stored as duplicated
// (v,v) pairs so the broadcast fma2 operand is a single LDS.64.
// smem = 96*130 floats = 49.9 KB -> 4 CTAs/SM, grid 392 = one wave.
// ---------------------------------------------------------------------------
#define XD 130
#define AD_SMEM_FLOATS (96 * XD)

extern "C" __global__ void __launch_bounds__(192)
adapter_kernel(const float* __restrict__ x,
               const float* __restrict__ W1, const float* __restrict__ b1,
               const float* __restrict__ W2, const float* __restrict__ b2) {
    extern __shared__ float sm[];
    float* Xs2 = sm;            // [il][2r] duplicated pairs, stride XD floats

    const int t   = threadIdx.x;
    const int tc  = t % 12;           // col group
    const int rg  = t / 12;           // row group
    const int j0  = tc * 8;
    const int r0  = rg * 4;
    const int row0 = blockIdx.x * 64; // 392 blocks * 64 = 25088 rows

    ull acc[4][4];
#pragma unroll
    for (int r = 0; r < 4; ++r)
#pragma unroll
        for (int p = 0; p < 4; ++p) acc[r][p] = 0ull;

    // ---- phase 1: hid = x @ W1 over 4 i-tiles of 96 ----
    for (int it = 0; it < 4; ++it) {
        __syncthreads();
        for (int idx = t; idx < 6144; idx += 192) {
            int il = idx % 96, r = idx / 96;
            float v = x[(size_t)(row0 + r) * DIMc + it * 96 + il];
            *(float2*)&Xs2[il * XD + 2 * r] = make_float2(v, v);
        }
        __syncthreads();
        const char* w1t = (const char*)(W1 + (size_t)it * 9216 + j0);
#pragma unroll 4
        for (int il = 0; il < 96; ++il) {
            const ulonglong2* wrow = (const ulonglong2*)(w1t + (size_t)il * 384);
            ulonglong2 wA = __ldg(wrow);
            ulonglong2 wB = __ldg(wrow + 1);
            const float* xr = &Xs2[il * XD + 2 * r0];
            ull xd0 = *(const ull*)&xr[0];
            ull xd1 = *(const ull*)&xr[2];
            ull xd2 = *(const ull*)&xr[4];
            ull xd3 = *(const ull*)&xr[6];
            acc[0][0] = fma2(wA.x, xd0, acc[0][0]);
            acc[0][1] = fma2(wA.y, xd0, acc[0][1]);
            acc[0][2] = fma2(wB.x, xd0, acc[0][2]);
            acc[0][3] = fma2(wB.y, xd0, acc[0][3]);
            acc[1][0] = fma2(wA.x, xd1, acc[1][0]);
            acc[1][1] = fma2(wA.y, xd1, acc[1][1]);
            acc[1][2] = fma2(wB.x, xd1, acc[1][2]);
            acc[1][3] = fma2(wB.y, xd1, acc[1][3]);
            acc[2][0] = fma2(wA.x, xd2, acc[2][0]);
            acc[2][1] = fma2(wA.y, xd2, acc[2][1]);
            acc[2][2] = fma2(wB.x, xd2, acc[2][2]);
            acc[2][3] = fma2(wB.y, xd2, acc[2][3]);
            acc[3][0] = fma2(wA.x, xd3, acc[3][0]);
            acc[3][1] = fma2(wA.y, xd3, acc[3][1]);
            acc[3][2] = fma2(wB.x, xd3, acc[3][2]);
            acc[3][3] = fma2(wB.y, xd3, acc[3][3]);
        }
    }
    __syncthreads();

    // ---- GELU(exact) + write Hs2 (duplicated pairs) ----
    float* Hs2 = Xs2;  // [i][2r] duplicated, stride XD
#pragma unroll
    for (int r = 0; r < 4; ++r)
#pragma unroll
        for (int p = 0; p < 4; ++p) {
            float2 v = unpack2(acc[r][p]);
            int j = j0 + 2 * p;
            float a0 = v.x + __ldg(&b1[j]);
            float a1 = v.y + __ldg(&b1[j + 1]);
            a0 = 0.5f * a0 * (1.0f + erff(a0 * 0.7071067811865476f));
            a1 = 0.5f * a1 * (1.0f + erff(a1 * 0.7071067811865476f));
            *(float2*)&Hs2[(size_t)j       * XD + 2 * (r0 + r)] = make_float2(a0, a0);
            *(float2*)&Hs2[(size_t)(j + 1) * XD + 2 * (r0 + r)] = make_float2(a1, a1);
        }
    __syncthreads();

    // ---- phase 2: mix = hid @ W2 (W2 via LDG, L1-hot) ----
    ull acc2[4][4];
#pragma unroll
    for (int r = 0; r < 4; ++r)
#pragma unroll
        for (int p = 0; p < 4; ++p) acc2[r][p] = 0ull;
    const char* w2t = (const char*)(W2 + j0);
#pragma unroll 4
    for (int i = 0; i < 96; ++i) {
        const ulonglong2* wrow = (const ulonglong2*)(w2t + (size_t)i * 384);
        ulonglong2 wA = __ldg(wrow);
        ulonglong2 wB = __ldg(wrow + 1);
        const float* hr = &Hs2[i * XD + 2 * r0];
        ull xd0 = *(const ull*)&hr[0];
        ull xd1 = *(const ull*)&hr[2];
        ull xd2 = *(const ull*)&hr[4];
        ull xd3 = *(const ull*)&hr[6];
        acc2[0][0] = fma2(wA.x, xd0, acc2[0][0]);
        acc2[0][1] = fma2(wA.y, xd0, acc2[0][1]);
        acc2[0][2] = fma2(wB.x, xd0, acc2[0][2]);
        acc2[0][3] = fma2(wB.y, xd0, acc2[0][3]);
        acc2[1][0] = fma2(wA.x, xd1, acc2[1][0]);
        acc2[1][1] = fma2(wA.y, xd1, acc2[1][1]);
        acc2[1][2] = fma2(wB.x, xd1, acc2[1][2]);
        acc2[1][3] = fma2(wB.y, xd1, acc2[1][3]);
        acc2[2][0] = fma2(wA.x, xd2, acc2[2][0]);
        acc2[2][1] = fma2(wA.y, xd2, acc2[2][1]);
        acc2[2][2] = fma2(wB.x, xd2, acc2[2][2]);
        acc2[2][3] = fma2(wB.y, xd2, acc2[2][3]);
        acc2[3][0] = fma2(wA.x, xd3, acc2[3][0]);
        acc2[3][1] = fma2(wA.y, xd3, acc2[3][1]);
        acc2[3][2] = fma2(wB.x, xd3, acc2[3][2]);
        acc2[3][3] = fma2(wB.y, xd3, acc2[3][3]);
    }
    __syncthreads();

    // ---- + b2, stage to Ms (reuse smem), softmax over k ----
    float* Ms = Xs2;  // 64*96 = 6144 floats, fits
#pragma unroll
    for (int r = 0; r < 4; ++r)
#pragma unroll
        for (int p = 0; p < 4; ++p) {
            float2 v = unpack2(acc2[r][p]);
            int j = j0 + 2 * p;
            Ms[(r0 + r) * 96 + j]     = v.x + __ldg(&b2[j]);
            Ms[(r0 + r) * 96 + j + 1] = v.y + __ldg(&b2[j + 1]);
        }
    __syncthreads();

    for (int g = t; g < 384; g += 192) {
        int r = g / 6, h = g % 6;
        float vals[Kk];
        float vmax = -1e30f;
#pragma unroll
        for (int k = 0; k < Kk; ++k) {
            vals[k] = Ms[r * 96 + k * Hh + h];
            vmax = fmaxf(vmax, vals[k]);
        }
        float s = 0.f;
#pragma unroll
        for (int k = 0; k < Kk; ++k) { vals[k] = __expf(vals[k] - vmax); s += vals[k]; }
        float inv = 1.0f / s;
        size_t base = ((size_t)(row0 + r) * Hh + h) * Kk;
#pragma unroll
        for (int k = 0; k < Kk; ++k) g_mix[base + k] = vals[k] * inv;
    }
}

// ---------------------------------------------------------------------------
// Kernel 3: fused mixer v3 (unchanged from R6 — measured win).
// Block = (m-tile of 28, batch b), 384 threads, 2 CTAs/SM.
// ---------------------------------------------------------------------------
#define MX_XS   10752
#define MX_MIX  2688
#define MX_WS   5376
#define MX_SMEM_FLOATS (MX_XS + MX_MIX + MX_WS)

extern "C" __global__ void __launch_bounds__(384, 2)
mixer_kernel(const float* __restrict__ x, float* __restrict__ out) {
    extern __shared__ float sm[];
    float* xs    = sm;                     // [nl][384]
    float* mix_s = sm + MX_XS;             // [nl][96]  ([h][k] inner)
    float* ws    = sm + MX_XS + MX_MIX;    // [nl][h][32] (m padded 28->32)

    const int t  = threadIdx.x;
    const int b  = blockIdx.y;
    const int mt = blockIdx.x;    // 0..6
    const int h  = t >> 6;

    ull acc[14];
#pragma unroll
    for (int q = 0; q < 14; ++q) acc[q] = 0ull;

    for (int c = 0; c < NCH; ++c) {
        const int n0 = c * CH;
        __syncthreads();
        // stage x chunk: 28*384 floats = 2688 float4, 7 per thread
        {
            const float4* src = (const float4*)(x + ((size_t)b * Nn + n0) * DIMc);
            float4* dst = (float4*)xs;
#pragma unroll
            for (int i = 0; i < 7; ++i) dst[t + i * 384] = src[t + i * 384];
        }
        // stage mix chunk: 28*96 floats = 672 float4
        {
            const float4* src = (const float4*)&g_mix[((size_t)b * Nn + n0) * 96];
            float4* dst = (float4*)mix_s;
            for (int idx = t; idx < 672; idx += 384) dst[idx] = src[idx];
        }
        __syncthreads();
        // phase 1: 784 (nl, ml) pairs over 384 threads
        for (int p = t; p < CH * TMX; p += 384) {
            int nl = p / TMX, ml = p - nl * TMX;
            int mg = mt * TMX + ml;
            const float4* wv = (const float4*)&g_wbt[((size_t)(n0 + nl) * Nn + mg) * Kk];
            float4 w0 = __ldg(wv + 0), w1 = __ldg(wv + 1);
            float4 w2 = __ldg(wv + 2), w3 = __ldg(wv + 3);
#pragma unroll
            for (int hh = 0; hh < Hh; ++hh) {
                const float4* mx = (const float4*)&mix_s[nl * 96 + hh * Kk];
                float4 m0 = mx[0], m1 = mx[1], m2 = mx[2], m3 = mx[3];
                float s = w0.x * m0.x;
                s = fmaf(w0.y, m0.y, s); s = fmaf(w0.z, m0.z, s); s = fmaf(w0.w, m0.w, s);
                s = fmaf(w1.x, m1.x, s); s = fmaf(w1.y, m1.y, s); s = fmaf(w1.z, m1.z, s); s = fmaf(w1.w, m1.w, s);
                s = fmaf(w2.x, m2.x, s); s = fmaf(w2.y, m2.y, s); s = fmaf(w2.z, m2.z, s); s = fmaf(w2.w, m2.w, s);
                s = fmaf(w3.x, m3.x, s); s = fmaf(w3.y, m3.y, s); s = fmaf(w3.z, m3.z, s); s = fmaf(w3.w, m3.w, s);
                ws[(nl * Hh + hh) * 32 + ml] = s;
            }
        }
        __syncthreads();
        // phase 2: all operands in smem; 14 f32x2 accumulators over 28 m
#pragma unroll 4
        for (int nl = 0; nl < CH; ++nl) {
            float xv = xs[nl * 384 + t];
            ull xx = pack2(xv, xv);
            const float* wr = &ws[(nl * Hh + h) * 32];
            ulonglong2 wA = *(const ulonglong2*)&wr[0];
            ulonglong2 wB = *(const ulonglong2*)&wr[4];
            ulonglong2 wC = *(const ulonglong2*)&wr[8];
            ulonglong2 wD = *(const ulonglong2*)&wr[12];
            ulonglong2 wE = *(const ulonglong2*)&wr[16];
            ulonglong2 wF = *(const ulonglong2*)&wr[20];
            ulonglong2 wG = *(const ulonglong2*)&wr[24];
            acc[0]  = fma2(wA.x, xx, acc[0]);
            acc[1]  = fma2(wA.y, xx, acc[1]);
            acc[2]  = fma2(wB.x, xx, acc[2]);
            acc[3]  = fma2(wB.y, xx, acc[3]);
            acc[4]  = fma2(wC.x, xx, acc[4]);
            acc[5]  = fma2(wC.y, xx, acc[5]);
            acc[6]  = fma2(wD.x, xx, acc[6]);
            acc[7]  = fma2(wD.y, xx, acc[7]);
            acc[8]  = fma2(wE.x, xx, acc[8]);
            acc[9]  = fma2(wE.y, xx, acc[9]);
            acc[10] = fma2(wF.x, xx, acc[10]);
            acc[11] = fma2(wF.y, xx, acc[11]);
            acc[12] = fma2(wG.x, xx, acc[12]);
            acc[13] = fma2(wG.y, xx, acc[13]);
        }
    }

    float* ob = out + ((size_t)b * Nn + mt * TMX) * DIMc + t;
#pragma unroll
    for (int q = 0; q < 14; ++q) {
        float2 v = unpack2(acc[q]);
        ob[(size_t)(2 * q)     * DIMc] = v.x;
        ob[(size_t)(2 * q + 1) * DIMc] = v.y;
    }
}

// ---------------------------------------------------------------------------
extern "C" void kernel_launch(void* const* d_in, const int* in_sizes, int n_in,
                              void* d_out, int out_size) {
    const float* x  = (const float*)d_in[0];
    const float* W1 = (const float*)d_in[1];
    const float* b1 = (const float*)d_in[2];
    const float* W2 = (const float*)d_in[3];
    const float* b2 = (const float*)d_in[4];
    const float* wb = (const float*)d_in[5];
    float* out = (float*)d_out;

    cudaFuncSetAttribute((const void*)adapter_kernel,
                         cudaFuncAttributeMaxDynamicSharedMemorySize,
                         AD_SMEM_FLOATS * 4);
    cudaFuncSetAttribute((const void*)mixer_kernel,
                         cudaFuncAttributeMaxDynamicSharedMemorySize,
                         MX_SMEM_FLOATS * 4);

    transpose_wb_kernel<<<(Nn * Nn + 255) / 256, 256>>>(wb);
    adapter_kernel<<<392, 192, AD_SMEM_FLOATS * 4>>>(x, W1, b1, W2, b2);
    mixer_kernel<<<dim3(NCH, Bz), 384, MX_SMEM_FLOATS * 4>>>(x, out);
}

// round 9
// speedup vs baseline: 1.7526x; 1.0408x over previous
#include <cuda_runtime.h>
#include <cstdint>

#define Bz   128
#define Nn   196
#define DIMc 384
#define Kk   16
#define Hh   6
#define DR   96
#define TMX  28   // mixer m-tile width; 7*28 == 196
#define CH   28   // mixer n-chunk; 7*28 == 196
#define NCH  7

// Scratch (device globals — allocation-free)
__device__ __align__(16) float g_wbt[(size_t)Nn * Nn * Kk];      // [n][m][k]
__device__ __align__(16) float g_mix[(size_t)Bz * Nn * Hh * Kk]; // [b][n][h][k]

typedef unsigned long long ull;

__device__ __forceinline__ ull fma2(ull a, ull b, ull c) {
    ull d;
    asm("fma.rn.f32x2 %0, %1, %2, %3;" : "=l"(d) : "l"(a), "l"(b), "l"(c));
    return d;
}
__device__ __forceinline__ ull mul2(ull a, ull b) {
    ull d;
    asm("mul.rn.f32x2 %0, %1, %2;" : "=l"(d) : "l"(a), "l"(b));
    return d;
}
__device__ __forceinline__ ull add2(ull a, ull b) {
    ull d;
    asm("add.rn.f32x2 %0, %1, %2;" : "=l"(d) : "l"(a), "l"(b));
    return d;
}
__device__ __forceinline__ ull pack2(float lo, float hi) {
    ull d;
    asm("mov.b64 %0, {%1, %2};" : "=l"(d) : "r"(__float_as_uint(lo)), "r"(__float_as_uint(hi)));
    return d;
}
__device__ __forceinline__ float2 unpack2(ull v) {
    unsigned lo, hi;
    asm("mov.b64 {%0, %1}, %2;" : "=r"(lo), "=r"(hi) : "l"(v));
    return make_float2(__uint_as_float(lo), __uint_as_float(hi));
}

// ---------------------------------------------------------------------------
// Kernel 1: weight_bank [k][n][m] -> g_wbt [n][m][k]  (k contiguous)
// ---------------------------------------------------------------------------
extern "C" __global__ void transpose_wb_kernel(const float* __restrict__ wb) {
    int t = blockIdx.x * 256 + threadIdx.x;
    if (t >= Nn * Nn) return;
    int n = t / Nn, m = t % Nn;
    float v[Kk];
#pragma unroll
    for (int k = 0; k < Kk; ++k)
        v[k] = wb[((size_t)k * Nn + n) * Nn + m];   // coalesced over m
    float4* dst = (float4*)&g_wbt[(size_t)t * Kk];
    dst[0] = make_float4(v[0],  v[1],  v[2],  v[3]);
    dst[1] = make_float4(v[4],  v[5],  v[6],  v[7]);
    dst[2] = make_float4(v[8],  v[9],  v[10], v[11]);
    dst[3] = make_float4(v[12], v[13], v[14], v[15]);
}

// ---------------------------------------------------------------------------
// Kernel 2: adapter (R5 version — best measured: 120.9us).
// 64 rows/block, 192 threads (12 colgroups x 16 rowgroups).
// hid = gelu(x@W1+b1); mix = hid@W2+b2; softmax over k; -> g_mix[b][n][h][k]
// smem: Ws 9216 floats (W1 tile / W2 / Ms), Xs 96*68 floats (X tile / Hs)
// ---------------------------------------------------------------------------
#define AD_SMEM_FLOATS (9216 + 96*68)

extern "C" __global__ void __launch_bounds__(192)
adapter_kernel(const float* __restrict__ x,
               const float* __restrict__ W1, const float* __restrict__ b1,
               const float* __restrict__ W2, const float* __restrict__ b2) {
    extern __shared__ float sm[];
    float* Ws = sm;            // 9216 floats (96x96)
    float* Xs = sm + 9216;     // 96 x 68 (padded), reused as Hs

    const int t   = threadIdx.x;
    const int tc  = t % 12;           // col group
    const int rg  = t / 12;           // row group
    const int j0  = tc * 8;
    const int r0  = rg * 4;
    const int row0 = blockIdx.x * 64; // 392 blocks * 64 = 25088 rows

    ull acc[4][4];
#pragma unroll
    for (int r = 0; r < 4; ++r)
#pragma unroll
        for (int p = 0; p < 4; ++p) acc[r][p] = 0ull;

    // ---- phase 1: hid = x @ W1 over 4 i-tiles of 96 ----
    for (int it = 0; it < 4; ++it) {
        __syncthreads();
        for (int idx = t; idx < 9216; idx += 192)
            Ws[idx] = W1[(size_t)it * 96 * 96 + idx];
        for (int idx = t; idx < 6144; idx += 192) {
            int il = idx % 96, r = idx / 96;
            Xs[il * 68 + r] = x[(size_t)(row0 + r) * DIMc + it * 96 + il];
        }
        __syncthreads();
#pragma unroll 4
        for (int il = 0; il < 96; ++il) {
            const ulonglong2 wA = *(const ulonglong2*)&Ws[il * 96 + j0];
            const ulonglong2 wB = *(const ulonglong2*)&Ws[il * 96 + j0 + 4];
            const float4 xv = *(const float4*)&Xs[il * 68 + r0];
            ull xd0 = pack2(xv.x, xv.x), xd1 = pack2(xv.y, xv.y);
            ull xd2 = pack2(xv.z, xv.z), xd3 = pack2(xv.w, xv.w);
            acc[0][0] = fma2(wA.x, xd0, acc[0][0]);
            acc[0][1] = fma2(wA.y, xd0, acc[0][1]);
            acc[0][2] = fma2(wB.x, xd0, acc[0][2]);
            acc[0][3] = fma2(wB.y, xd0, acc[0][3]);
            acc[1][0] = fma2(wA.x, xd1, acc[1][0]);
            acc[1][1] = fma2(wA.y, xd1, acc[1][1]);
            acc[1][2] = fma2(wB.x, xd1, acc[1][2]);
            acc[1][3] = fma2(wB.y, xd1, acc[1][3]);
            acc[2][0] = fma2(wA.x, xd2, acc[2][0]);
            acc[2][1] = fma2(wA.y, xd2, acc[2][1]);
            acc[2][2] = fma2(wB.x, xd2, acc[2][2]);
            acc[2][3] = fma2(wB.y, xd2, acc[2][3]);
            acc[3][0] = fma2(wA.x, xd3, acc[3][0]);
            acc[3][1] = fma2(wA.y, xd3, acc[3][1]);
            acc[3][2] = fma2(wB.x, xd3, acc[3][2]);
            acc[3][3] = fma2(wB.y, xd3, acc[3][3]);
        }
    }
    __syncthreads();

    // ---- GELU(exact) + write Hs (transposed) ; load W2 into Ws ----
    for (int idx = t; idx < 9216; idx += 192) Ws[idx] = W2[idx];
    float* Hs = Xs;
#pragma unroll
    for (int r = 0; r < 4; ++r)
#pragma unroll
        for (int p = 0; p < 4; ++p) {
            float2 v = unpack2(acc[r][p]);
            int j = j0 + 2 * p;
            float a0 = v.x + b1[j];
            float a1 = v.y + b1[j + 1];
            a0 = 0.5f * a0 * (1.0f + erff(a0 * 0.7071067811865476f));
            a1 = 0.5f * a1 * (1.0f + erff(a1 * 0.7071067811865476f));
            Hs[(size_t)j       * 68 + r0 + r] = a0;
            Hs[(size_t)(j + 1) * 68 + r0 + r] = a1;
        }
    __syncthreads();

    // ---- phase 2: mix = hid @ W2 ----
    ull acc2[4][4];
#pragma unroll
    for (int r = 0; r < 4; ++r)
#pragma unroll
        for (int p = 0; p < 4; ++p) acc2[r][p] = 0ull;
#pragma unroll 4
    for (int i = 0; i < 96; ++i) {
        const ulonglong2 wA = *(const ulonglong2*)&Ws[i * 96 + j0];
        const ulonglong2 wB = *(const ulonglong2*)&Ws[i * 96 + j0 + 4];
        const float4 hv = *(const float4*)&Hs[i * 68 + r0];
        ull xd0 = pack2(hv.x, hv.x), xd1 = pack2(hv.y, hv.y);
        ull xd2 = pack2(hv.z, hv.z), xd3 = pack2(hv.w, hv.w);
        acc2[0][0] = fma2(wA.x, xd0, acc2[0][0]);
        acc2[0][1] = fma2(wA.y, xd0, acc2[0][1]);
        acc2[0][2] = fma2(wB.x, xd0, acc2[0][2]);
        acc2[0][3] = fma2(wB.y, xd0, acc2[0][3]);
        acc2[1][0] = fma2(wA.x, xd1, acc2[1][0]);
        acc2[1][1] = fma2(wA.y, xd1, acc2[1][1]);
        acc2[1][2] = fma2(wB.x, xd1, acc2[1][2]);
        acc2[1][3] = fma2(wB.y, xd1, acc2[1][3]);
        acc2[2][0] = fma2(wA.x, xd2, acc2[2][0]);
        acc2[2][1] = fma2(wA.y, xd2, acc2[2][1]);
        acc2[2][2] = fma2(wB.x, xd2, acc2[2][2]);
        acc2[2][3] = fma2(wB.y, xd2, acc2[2][3]);
        acc2[3][0] = fma2(wA.x, xd3, acc2[3][0]);
        acc2[3][1] = fma2(wA.y, xd3, acc2[3][1]);
        acc2[3][2] = fma2(wB.x, xd3, acc2[3][2]);
        acc2[3][3] = fma2(wB.y, xd3, acc2[3][3]);
    }
    __syncthreads();

    // ---- + b2, stage to Ms, softmax over k ----
    float* Ms = Ws;
#pragma unroll
    for (int r = 0; r < 4; ++r)
#pragma unroll
        for (int p = 0; p < 4; ++p) {
            float2 v = unpack2(acc2[r][p]);
            int j = j0 + 2 * p;
            Ms[(r0 + r) * 96 + j]     = v.x + b2[j];
            Ms[(r0 + r) * 96 + j + 1] = v.y + b2[j + 1];
        }
    __syncthreads();

    for (int g = t; g < 384; g += 192) {
        int r = g / 6, h = g % 6;
        float vals[Kk];
        float vmax = -1e30f;
#pragma unroll
        for (int k = 0; k < Kk; ++k) {
            vals[k] = Ms[r * 96 + k * Hh + h];
            vmax = fmaxf(vmax, vals[k]);
        }
        float s = 0.f;
#pragma unroll
        for (int k = 0; k < Kk; ++k) { vals[k] = __expf(vals[k] - vmax); s += vals[k]; }
        float inv = 1.0f / s;
        size_t base = ((size_t)(row0 + r) * Hh + h) * Kk;
#pragma unroll
        for (int k = 0; k < Kk; ++k) g_mix[base + k] = vals[k] * inv;
    }
}

// ---------------------------------------------------------------------------
// Kernel 3: fused mixer v4 — phase 1 dot-16 converted to f32x2 (two chains).
// Block = (m-tile of 28, batch b), 384 threads, 2 CTAs/SM.
// ---------------------------------------------------------------------------
#define MX_XS   10752
#define MX_MIX  2688
#define MX_WS   5376
#define MX_SMEM_FLOATS (MX_XS + MX_MIX + MX_WS)

extern "C" __global__ void __launch_bounds__(384, 2)
mixer_kernel(const float* __restrict__ x, float* __restrict__ out) {
    extern __shared__ float sm[];
    float* xs    = sm;                     // [nl][384]
    float* mix_s = sm + MX_XS;             // [nl][96]  ([h][k] inner)
    float* ws    = sm + MX_XS + MX_MIX;    // [nl][h][32] (m padded 28->32)

    const int t  = threadIdx.x;
    const int b  = blockIdx.y;
    const int mt = blockIdx.x;    // 0..6
    const int h  = t >> 6;

    ull acc[14];
#pragma unroll
    for (int q = 0; q < 14; ++q) acc[q] = 0ull;

    for (int c = 0; c < NCH; ++c) {
        const int n0 = c * CH;
        __syncthreads();
        // stage x chunk: 28*384 floats = 2688 float4, 7 per thread
        {
            const float4* src = (const float4*)(x + ((size_t)b * Nn + n0) * DIMc);
            float4* dst = (float4*)xs;
#pragma unroll
            for (int i = 0; i < 7; ++i) dst[t + i * 384] = src[t + i * 384];
        }
        // stage mix chunk: 28*96 floats = 672 float4
        {
            const float4* src = (const float4*)&g_mix[((size_t)b * Nn + n0) * 96];
            float4* dst = (float4*)mix_s;
            for (int idx = t; idx < 672; idx += 384) dst[idx] = src[idx];
        }
        __syncthreads();
        // phase 1: 784 (nl, ml) pairs over 384 threads; dot-16 via f32x2
        for (int p = t; p < CH * TMX; p += 384) {
            int nl = p / TMX, ml = p - nl * TMX;
            int mg = mt * TMX + ml;
            const ulonglong2* wv = (const ulonglong2*)&g_wbt[((size_t)(n0 + nl) * Nn + mg) * Kk];
            ulonglong2 w01 = __ldg(wv + 0);   // k pairs 0,1
            ulonglong2 w23 = __ldg(wv + 1);   // k pairs 2,3
            ulonglong2 w45 = __ldg(wv + 2);   // k pairs 4,5
            ulonglong2 w67 = __ldg(wv + 3);   // k pairs 6,7
#pragma unroll
            for (int hh = 0; hh < Hh; ++hh) {
                const ulonglong2* mx = (const ulonglong2*)&mix_s[nl * 96 + hh * Kk];
                ulonglong2 m01 = mx[0], m23 = mx[1], m45 = mx[2], m67 = mx[3];
                ull sa = mul2(w01.x, m01.x);
                ull sb = mul2(w01.y, m01.y);
                sa = fma2(w23.x, m23.x, sa);
                sb = fma2(w23.y, m23.y, sb);
                sa = fma2(w45.x, m45.x, sa);
                sb = fma2(w45.y, m45.y, sb);
                sa = fma2(w67.x, m67.x, sa);
                sb = fma2(w67.y, m67.y, sb);
                float2 f = unpack2(add2(sa, sb));
                ws[(nl * Hh + hh) * 32 + ml] = f.x + f.y;
            }
        }
        __syncthreads();
        // phase 2: all operands in smem; 14 f32x2 accumulators over 28 m
#pragma unroll 4
        for (int nl = 0; nl < CH; ++nl) {
            float xv = xs[nl * 384 + t];
            ull xx = pack2(xv, xv);
            const float* wr = &ws[(nl * Hh + h) * 32];
            ulonglong2 wA = *(const ulonglong2*)&wr[0];
            ulonglong2 wB = *(const ulonglong2*)&wr[4];
            ulonglong2 wC = *(const ulonglong2*)&wr[8];
            ulonglong2 wD = *(const ulonglong2*)&wr[12];
            ulonglong2 wE = *(const ulonglong2*)&wr[16];
            ulonglong2 wF = *(const ulonglong2*)&wr[20];
            ulonglong2 wG = *(const ulonglong2*)&wr[24];
            acc[0]  = fma2(wA.x, xx, acc[0]);
            acc[1]  = fma2(wA.y, xx, acc[1]);
            acc[2]  = fma2(wB.x, xx, acc[2]);
            acc[3]  = fma2(wB.y, xx, acc[3]);
            acc[4]  = fma2(wC.x, xx, acc[4]);
            acc[5]  = fma2(wC.y, xx, acc[5]);
            acc[6]  = fma2(wD.x, xx, acc[6]);
            acc[7]  = fma2(wD.y, xx, acc[7]);
            acc[8]  = fma2(wE.x, xx, acc[8]);
            acc[9]  = fma2(wE.y, xx, acc[9]);
            acc[10] = fma2(wF.x, xx, acc[10]);
            acc[11] = fma2(wF.y, xx, acc[11]);
            acc[12] = fma2(wG.x, xx, acc[12]);
            acc[13] = fma2(wG.y, xx, acc[13]);
        }
    }

    float* ob = out + ((size_t)b * Nn + mt * TMX) * DIMc + t;
#pragma unroll
    for (int q = 0; q < 14; ++q) {
        float2 v = unpack2(acc[q]);
        ob[(size_t)(2 * q)     * DIMc] = v.x;
        ob[(size_t)(2 * q + 1) * DIMc] = v.y;
    }
}

// ---------------------------------------------------------------------------
extern "C" void kernel_launch(void* const* d_in, const int* in_sizes, int n_in,
                              void* d_out, int out_size) {
    const float* x  = (const float*)d_in[0];
    const float* W1 = (const float*)d_in[1];
    const float* b1 = (const float*)d_in[2];
    const float* W2 = (const float*)d_in[3];
    const float* b2 = (const float*)d_in[4];
    const float* wb = (const float*)d_in[5];
    float* out = (float*)d_out;

    cudaFuncSetAttribute((const void*)adapter_kernel,
                         cudaFuncAttributeMaxDynamicSharedMemorySize,
                         AD_SMEM_FLOATS * 4);
    cudaFuncSetAttribute((const void*)mixer_kernel,
                         cudaFuncAttributeMaxDynamicSharedMemorySize,
                         MX_SMEM_FLOATS * 4);

    transpose_wb_kernel<<<(Nn * Nn + 255) / 256, 256>>>(wb);
    adapter_kernel<<<392, 192, AD_SMEM_FLOATS * 4>>>(x, W1, b1, W2, b2);
    mixer_kernel<<<dim3(NCH, Bz), 384, MX_SMEM_FLOATS * 4>>>(x, out);
}

// round 10
// speedup vs baseline: 1.8099x; 1.0327x over previous
#include <cuda_runtime.h>
#include <cstdint>

#define Bz   128
#define Nn   196
#define DIMc 384
#define Kk   16
#define Hh   6
#define DR   96
#define TMX  28   // mixer m-tile width; 7*28 == 196
#define CH   28   // mixer n-chunk; 7*28 == 196
#define NCH  7

// Scratch (device globals — allocation-free)
__device__ __align__(16) float g_wbt[(size_t)Nn * Nn * Kk];      // [n][m][k]
__device__ __align__(16) float g_mix[(size_t)Bz * Nn * Hh * Kk]; // [b][n][h][k]

typedef unsigned long long ull;

__device__ __forceinline__ ull fma2(ull a, ull b, ull c) {
    ull d;
    asm("fma.rn.f32x2 %0, %1, %2, %3;" : "=l"(d) : "l"(a), "l"(b), "l"(c));
    return d;
}
__device__ __forceinline__ ull pack2(float lo, float hi) {
    ull d;
    asm("mov.b64 %0, {%1, %2};" : "=l"(d) : "r"(__float_as_uint(lo)), "r"(__float_as_uint(hi)));
    return d;
}
__device__ __forceinline__ float2 unpack2(ull v) {
    unsigned lo, hi;
    asm("mov.b64 {%0, %1}, %2;" : "=r"(lo), "=r"(hi) : "l"(v));
    return make_float2(__uint_as_float(lo), __uint_as_float(hi));
}
__device__ __forceinline__ uint32_t smem_u32(const void* p) {
    uint32_t a;
    asm("{ .reg .u64 tmp; cvta.to.shared.u64 tmp, %1; cvt.u32.u64 %0, tmp; }"
        : "=r"(a) : "l"(p));
    return a;
}
__device__ __forceinline__ void cp_async16(uint32_t saddr, const void* gptr) {
    asm volatile("cp.async.ca.shared.global [%0], [%1], 16;"
                 :: "r"(saddr), "l"(gptr) : "memory");
}
#define CP_COMMIT() asm volatile("cp.async.commit_group;" ::: "memory")
#define CP_WAIT(n)  asm volatile("cp.async.wait_group %0;" :: "n"(n) : "memory")

// ---------------------------------------------------------------------------
// Kernel 1: weight_bank [k][n][m] -> g_wbt [n][m][k]  (k contiguous)
// ---------------------------------------------------------------------------
extern "C" __global__ void transpose_wb_kernel(const float* __restrict__ wb) {
    int t = blockIdx.x * 256 + threadIdx.x;
    if (t >= Nn * Nn) return;
    int n = t / Nn, m = t % Nn;
    float v[Kk];
#pragma unroll
    for (int k = 0; k < Kk; ++k)
        v[k] = wb[((size_t)k * Nn + n) * Nn + m];   // coalesced over m
    float4* dst = (float4*)&g_wbt[(size_t)t * Kk];
    dst[0] = make_float4(v[0],  v[1],  v[2],  v[3]);
    dst[1] = make_float4(v[4],  v[5],  v[6],  v[7]);
    dst[2] = make_float4(v[8],  v[9],  v[10], v[11]);
    dst[3] = make_float4(v[12], v[13], v[14], v[15]);
}

// ---------------------------------------------------------------------------
// Kernel 2: adapter (best measured: 120.9us). UNCHANGED.
// 64 rows/block, 192 threads (12 colgroups x 16 rowgroups).
// ---------------------------------------------------------------------------
#define AD_SMEM_FLOATS (9216 + 96*68)

extern "C" __global__ void __launch_bounds__(192)
adapter_kernel(const float* __restrict__ x,
               const float* __restrict__ W1, const float* __restrict__ b1,
               const float* __restrict__ W2, const float* __restrict__ b2) {
    extern __shared__ float sm[];
    float* Ws = sm;            // 9216 floats (96x96)
    float* Xs = sm + 9216;     // 96 x 68 (padded), reused as Hs

    const int t   = threadIdx.x;
    const int tc  = t % 12;           // col group
    const int rg  = t / 12;           // row group
    const int j0  = tc * 8;
    const int r0  = rg * 4;
    const int row0 = blockIdx.x * 64; // 392 blocks * 64 = 25088 rows

    ull acc[4][4];
#pragma unroll
    for (int r = 0; r < 4; ++r)
#pragma unroll
        for (int p = 0; p < 4; ++p) acc[r][p] = 0ull;

    // ---- phase 1: hid = x @ W1 over 4 i-tiles of 96 ----
    for (int it = 0; it < 4; ++it) {
        __syncthreads();
        for (int idx = t; idx < 9216; idx += 192)
            Ws[idx] = W1[(size_t)it * 96 * 96 + idx];
        for (int idx = t; idx < 6144; idx += 192) {
            int il = idx % 96, r = idx / 96;
            Xs[il * 68 + r] = x[(size_t)(row0 + r) * DIMc + it * 96 + il];
        }
        __syncthreads();
#pragma unroll 4
        for (int il = 0; il < 96; ++il) {
            const ulonglong2 wA = *(const ulonglong2*)&Ws[il * 96 + j0];
            const ulonglong2 wB = *(const ulonglong2*)&Ws[il * 96 + j0 + 4];
            const float4 xv = *(const float4*)&Xs[il * 68 + r0];
            ull xd0 = pack2(xv.x, xv.x), xd1 = pack2(xv.y, xv.y);
            ull xd2 = pack2(xv.z, xv.z), xd3 = pack2(xv.w, xv.w);
            acc[0][0] = fma2(wA.x, xd0, acc[0][0]);
            acc[0][1] = fma2(wA.y, xd0, acc[0][1]);
            acc[0][2] = fma2(wB.x, xd0, acc[0][2]);
            acc[0][3] = fma2(wB.y, xd0, acc[0][3]);
            acc[1][0] = fma2(wA.x, xd1, acc[1][0]);
            acc[1][1] = fma2(wA.y, xd1, acc[1][1]);
            acc[1][2] = fma2(wB.x, xd1, acc[1][2]);
            acc[1][3] = fma2(wB.y, xd1, acc[1][3]);
            acc[2][0] = fma2(wA.x, xd2, acc[2][0]);
            acc[2][1] = fma2(wA.y, xd2, acc[2][1]);
            acc[2][2] = fma2(wB.x, xd2, acc[2][2]);
            acc[2][3] = fma2(wB.y, xd2, acc[2][3]);
            acc[3][0] = fma2(wA.x, xd3, acc[3][0]);
            acc[3][1] = fma2(wA.y, xd3, acc[3][1]);
            acc[3][2] = fma2(wB.x, xd3, acc[3][2]);
            acc[3][3] = fma2(wB.y, xd3, acc[3][3]);
        }
    }
    __syncthreads();

    // ---- GELU(exact) + write Hs (transposed) ; load W2 into Ws ----
    for (int idx = t; idx < 9216; idx += 192) Ws[idx] = W2[idx];
    float* Hs = Xs;
#pragma unroll
    for (int r = 0; r < 4; ++r)
#pragma unroll
        for (int p = 0; p < 4; ++p) {
            float2 v = unpack2(acc[r][p]);
            int j = j0 + 2 * p;
            float a0 = v.x + b1[j];
            float a1 = v.y + b1[j + 1];
            a0 = 0.5f * a0 * (1.0f + erff(a0 * 0.7071067811865476f));
            a1 = 0.5f * a1 * (1.0f + erff(a1 * 0.7071067811865476f));
            Hs[(size_t)j       * 68 + r0 + r] = a0;
            Hs[(size_t)(j + 1) * 68 + r0 + r] = a1;
        }
    __syncthreads();

    // ---- phase 2: mix = hid @ W2 ----
    ull acc2[4][4];
#pragma unroll
    for (int r = 0; r < 4; ++r)
#pragma unroll
        for (int p = 0; p < 4; ++p) acc2[r][p] = 0ull;
#pragma unroll 4
    for (int i = 0; i < 96; ++i) {
        const ulonglong2 wA = *(const ulonglong2*)&Ws[i * 96 + j0];
        const ulonglong2 wB = *(const ulonglong2*)&Ws[i * 96 + j0 + 4];
        const float4 hv = *(const float4*)&Hs[i * 68 + r0];
        ull xd0 = pack2(hv.x, hv.x), xd1 = pack2(hv.y, hv.y);
        ull xd2 = pack2(hv.z, hv.z), xd3 = pack2(hv.w, hv.w);
        acc2[0][0] = fma2(wA.x, xd0, acc2[0][0]);
        acc2[0][1] = fma2(wA.y, xd0, acc2[0][1]);
        acc2[0][2] = fma2(wB.x, xd0, acc2[0][2]);
        acc2[0][3] = fma2(wB.y, xd0, acc2[0][3]);
        acc2[1][0] = fma2(wA.x, xd1, acc2[1][0]);
        acc2[1][1] = fma2(wA.y, xd1, acc2[1][1]);
        acc2[1][2] = fma2(wB.x, xd1, acc2[1][2]);
        acc2[1][3] = fma2(wB.y, xd1, acc2[1][3]);
        acc2[2][0] = fma2(wA.x, xd2, acc2[2][0]);
        acc2[2][1] = fma2(wA.y, xd2, acc2[2][1]);
        acc2[2][2] = fma2(wB.x, xd2, acc2[2][2]);
        acc2[2][3] = fma2(wB.y, xd2, acc2[2][3]);
        acc2[3][0] = fma2(wA.x, xd3, acc2[3][0]);
        acc2[3][1] = fma2(wA.y, xd3, acc2[3][1]);
        acc2[3][2] = fma2(wB.x, xd3, acc2[3][2]);
        acc2[3][3] = fma2(wB.y, xd3, acc2[3][3]);
    }
    __syncthreads();

    // ---- + b2, stage to Ms, softmax over k ----
    float* Ms = Ws;
#pragma unroll
    for (int r = 0; r < 4; ++r)
#pragma unroll
        for (int p = 0; p < 4; ++p) {
            float2 v = unpack2(acc2[r][p]);
            int j = j0 + 2 * p;
            Ms[(r0 + r) * 96 + j]     = v.x + b2[j];
            Ms[(r0 + r) * 96 + j + 1] = v.y + b2[j + 1];
        }
    __syncthreads();

    for (int g = t; g < 384; g += 192) {
        int r = g / 6, h = g % 6;
        float vals[Kk];
        float vmax = -1e30f;
#pragma unroll
        for (int k = 0; k < Kk; ++k) {
            vals[k] = Ms[r * 96 + k * Hh + h];
            vmax = fmaxf(vmax, vals[k]);
        }
        float s = 0.f;
#pragma unroll
        for (int k = 0; k < Kk; ++k) { vals[k] = __expf(vals[k] - vmax); s += vals[k]; }
        float inv = 1.0f / s;
        size_t base = ((size_t)(row0 + r) * Hh + h) * Kk;
#pragma unroll
        for (int k = 0; k < Kk; ++k) g_mix[base + k] = vals[k] * inv;
    }
}

// ---------------------------------------------------------------------------
// Kernel 3: fused mixer v5 — phase 1 reverted to v3 scalar dot-16 (measured
// best); NEW: cp.async staging. mix group committed first, x group second;
// wait_group 1 -> phase 1 runs while x still in flight; wait_group 0 before
// phase 2. Block = (m-tile of 28, batch b), 384 threads, 2 CTAs/SM.
// ---------------------------------------------------------------------------
#define MX_XS   10752
#define MX_MIX  2688
#define MX_WS   5376
#define MX_SMEM_FLOATS (MX_XS + MX_MIX + MX_WS)

extern "C" __global__ void __launch_bounds__(384, 2)
mixer_kernel(const float* __restrict__ x, float* __restrict__ out) {
    extern __shared__ float sm[];
    float* xs    = sm;                     // [nl][384]
    float* mix_s = sm + MX_XS;             // [nl][96]  ([h][k] inner)
    float* ws    = sm + MX_XS + MX_MIX;    // [nl][h][32] (m padded 28->32)

    const int t  = threadIdx.x;
    const int b  = blockIdx.y;
    const int mt = blockIdx.x;    // 0..6
    const int h  = t >> 6;

    const uint32_t xs_a  = smem_u32(xs);
    const uint32_t mix_a = smem_u32(mix_s);

    ull acc[14];
#pragma unroll
    for (int q = 0; q < 14; ++q) acc[q] = 0ull;

    for (int c = 0; c < NCH; ++c) {
        const int n0 = c * CH;
        __syncthreads();   // prior phase 2 done reading xs/ws before overwrite
        // group 1: mix chunk (672 float4)
        {
            const float4* src = (const float4*)&g_mix[((size_t)b * Nn + n0) * 96];
            cp_async16(mix_a + (uint32_t)t * 16u, src + t);
            if (t < 288) cp_async16(mix_a + (uint32_t)(384 + t) * 16u, src + 384 + t);
        }
        CP_COMMIT();
        // group 2: x chunk (2688 float4, 7 per thread)
        {
            const float4* src = (const float4*)(x + ((size_t)b * Nn + n0) * DIMc);
#pragma unroll
            for (int i = 0; i < 7; ++i)
                cp_async16(xs_a + (uint32_t)(t + i * 384) * 16u, src + t + i * 384);
        }
        CP_COMMIT();
        CP_WAIT(1);        // mix group landed; x may still be in flight
        __syncthreads();
        // phase 1 (scalar dot-16, v3 form): 784 (nl, ml) pairs over 384 threads
        for (int p = t; p < CH * TMX; p += 384) {
            int nl = p / TMX, ml = p - nl * TMX;
            int mg = mt * TMX + ml;
            const float4* wv = (const float4*)&g_wbt[((size_t)(n0 + nl) * Nn + mg) * Kk];
            float4 w0 = __ldg(wv + 0), w1 = __ldg(wv + 1);
            float4 w2 = __ldg(wv + 2), w3 = __ldg(wv + 3);
#pragma unroll
            for (int hh = 0; hh < Hh; ++hh) {
                const float4* mx = (const float4*)&mix_s[nl * 96 + hh * Kk];
                float4 m0 = mx[0], m1 = mx[1], m2 = mx[2], m3 = mx[3];
                float s = w0.x * m0.x;
                s = fmaf(w0.y, m0.y, s); s = fmaf(w0.z, m0.z, s); s = fmaf(w0.w, m0.w, s);
                s = fmaf(w1.x, m1.x, s); s = fmaf(w1.y, m1.y, s); s = fmaf(w1.z, m1.z, s); s = fmaf(w1.w, m1.w, s);
                s = fmaf(w2.x, m2.x, s); s = fmaf(w2.y, m2.y, s); s = fmaf(w2.z, m2.z, s); s = fmaf(w2.w, m2.w, s);
                s = fmaf(w3.x, m3.x, s); s = fmaf(w3.y, m3.y, s); s = fmaf(w3.z, m3.z, s); s = fmaf(w3.w, m3.w, s);
                ws[(nl * Hh + hh) * 32 + ml] = s;
            }
        }
        CP_WAIT(0);        // x chunk landed
        __syncthreads();   // ws + xs visible to all
        // phase 2: all operands in smem; 14 f32x2 accumulators over 28 m
#pragma unroll 4
        for (int nl = 0; nl < CH; ++nl) {
            float xv = xs[nl * 384 + t];
            ull xx = pack2(xv, xv);
            const float* wr = &ws[(nl * Hh + h) * 32];
            ulonglong2 wA = *(const ulonglong2*)&wr[0];
            ulonglong2 wB = *(const ulonglong2*)&wr[4];
            ulonglong2 wC = *(const ulonglong2*)&wr[8];
            ulonglong2 wD = *(const ulonglong2*)&wr[12];
            ulonglong2 wE = *(const ulonglong2*)&wr[16];
            ulonglong2 wF = *(const ulonglong2*)&wr[20];
            ulonglong2 wG = *(const ulonglong2*)&wr[24];
            acc[0]  = fma2(wA.x, xx, acc[0]);
            acc[1]  = fma2(wA.y, xx, acc[1]);
            acc[2]  = fma2(wB.x, xx, acc[2]);
            acc[3]  = fma2(wB.y, xx, acc[3]);
            acc[4]  = fma2(wC.x, xx, acc[4]);
            acc[5]  = fma2(wC.y, xx, acc[5]);
            acc[6]  = fma2(wD.x, xx, acc[6]);
            acc[7]  = fma2(wD.y, xx, acc[7]);
            acc[8]  = fma2(wE.x, xx, acc[8]);
            acc[9]  = fma2(wE.y, xx, acc[9]);
            acc[10] = fma2(wF.x, xx, acc[10]);
            acc[11] = fma2(wF.y, xx, acc[11]);
            acc[12] = fma2(wG.x, xx, acc[12]);
            acc[13] = fma2(wG.y, xx, acc[13]);
        }
    }

    float* ob = out + ((size_t)b * Nn + mt * TMX) * DIMc + t;
#pragma unroll
    for (int q = 0; q < 14; ++q) {
        float2 v = unpack2(acc[q]);
        ob[(size_t)(2 * q)     * DIMc] = v.x;
        ob[(size_t)(2 * q + 1) * DIMc] = v.y;
    }
}

// ---------------------------------------------------------------------------
extern "C" void kernel_launch(void* const* d_in, const int* in_sizes, int n_in,
                              void* d_out, int out_size) {
    const float* x  = (const float*)d_in[0];
    const float* W1 = (const float*)d_in[1];
    const float* b1 = (const float*)d_in[2];
    const float* W2 = (const float*)d_in[3];
    const float* b2 = (const float*)d_in[4];
    const float* wb = (const float*)d_in[5];
    float* out = (float*)d_out;

    cudaFuncSetAttribute((const void*)adapter_kernel,
                         cudaFuncAttributeMaxDynamicSharedMemorySize,
                         AD_SMEM_FLOATS * 4);
    cudaFuncSetAttribute((const void*)mixer_kernel,
                         cudaFuncAttributeMaxDynamicSharedMemorySize,
                         MX_SMEM_FLOATS * 4);

    transpose_wb_kernel<<<(Nn * Nn + 255) / 256, 256>>>(wb);
    adapter_kernel<<<392, 192, AD_SMEM_FLOATS * 4>>>(x, W1, b1, W2, b2);
    mixer_kernel<<<dim3(NCH, Bz), 384, MX_SMEM_FLOATS * 4>>>(x, out);
}